// round 13
// baseline (speedup 1.0000x reference)
#include <cuda_runtime.h>
#include <math.h>

#define Bb 8
#define Mm 1024
#define Ee 1536
#define Dd 256
#define Hh 8
#define DHd 32
#define D3 768
#define LNEPS 1e-5f

// -------------------- scratch (static __device__, no allocation) -----------
__device__ float g_qkv  [Bb*Mm*D3];
__device__ float g_ao   [Bb*Mm*Dd];
__device__ float g_attn [Bb*Mm*Dd];
__device__ float g_S    [Bb*Ee*Dd];
__device__ float g_E0   [Bb*Ee*Dd];
__device__ float g_wef  [Bb*Mm*Dd];
__device__ float g_csum [Bb*Dd];
__device__ float g_featr[Bb*Mm*Dd];
__device__ float g_wIn  [D3*Dd];
__device__ float g_wOut [Dd*Dd];
__device__ float g_wPv  [Dd*Dd];
__device__ float g_wPe  [Dd*Dd];

// -------------------- tf32 / async helpers ----------------------------------
__device__ __forceinline__ unsigned f2tf32(float x) {
    unsigned r;
    asm("cvt.rna.tf32.f32 %0, %1;" : "=r"(r) : "f"(x));
    return r;
}
__device__ __forceinline__ float round_tf32(float x) {
    return __uint_as_float(f2tf32(x));
}

__device__ __forceinline__ void mma_tf32(float c[4], const unsigned a[4], const unsigned b[2]) {
    asm volatile(
        "mma.sync.aligned.m16n8k8.row.col.f32.tf32.tf32.f32 "
        "{%0,%1,%2,%3}, {%4,%5,%6,%7}, {%8,%9}, {%0,%1,%2,%3};"
        : "+f"(c[0]), "+f"(c[1]), "+f"(c[2]), "+f"(c[3])
        : "r"(a[0]), "r"(a[1]), "r"(a[2]), "r"(a[3]), "r"(b[0]), "r"(b[1]));
}

__device__ __forceinline__ void cp_async16(void* smem_dst, const float* gsrc) {
    unsigned s = (unsigned)__cvta_generic_to_shared(smem_dst);
    asm volatile("cp.async.ca.shared.global [%0], [%1], 16;" :: "r"(s), "l"(gsrc));
}
#define CP_COMMIT() asm volatile("cp.async.commit_group;")

// -------------------- merged pre-round kernel (+ csum zero tail) ------------
__global__ void round_all_kernel(const float* __restrict__ f,
                                 const float* __restrict__ w1, const float* __restrict__ w2,
                                 const float* __restrict__ w3, const float* __restrict__ w4,
                                 float* __restrict__ of,
                                 float* __restrict__ o1, float* __restrict__ o2,
                                 float* __restrict__ o3, float* __restrict__ o4,
                                 float* __restrict__ csum) {
    const size_t NF = (size_t)Bb * Mm * Dd, N1 = (size_t)D3 * Dd, N2 = (size_t)Dd * Dd;
    size_t i = (size_t)blockIdx.x * 256 + threadIdx.x;
    if (i < NF) { of[i] = round_tf32(f[i]); return; }
    i -= NF;
    if (i < N1) { o1[i] = round_tf32(w1[i]); return; }
    i -= N1;
    if (i < N2) { o2[i] = round_tf32(w2[i]); return; }
    i -= N2;
    if (i < N2) { o3[i] = round_tf32(w3[i]); return; }
    i -= N2;
    if (i < N2) { o4[i] = round_tf32(w4[i]); return; }
    i -= N2;
    if (i < (size_t)Bb * Dd) csum[i] = 0.f;
}

// ============================================================================
// tf32 GEMM, cp.async 3-stage ring. Operands pre-rounded to tf32.
//   MTM: #16-row subtiles per warp (4 -> 128-row CTA tile, 2 -> 64-row).
//   TA==0: A stored [M,K]   TA==1: A stored [K,M]   (TA==1 requires MTM==4)
//   TB==0: B stored [N,K]   TB==1: B stored [K,N]
// 128 thr, 4 warps (2x2); warp tile (MTM*16) x 32. N tile = 64.
// SUMEXP: epilogue column-sums exp(acc) into csum[z*Dd + col] (atomic).
// ============================================================================
template<int MTM, int TA, int TB, bool HASBIAS, bool ROUND, bool SUMEXP>
__global__ void __launch_bounds__(128, (MTM == 4) ? 3 : 4) gemm_tf32_kernel(
    const float* __restrict__ A, const float* __restrict__ B,
    const float* __restrict__ bias, float* __restrict__ C,
    int M, int N, int K, int lda, int ldb,
    long sA, long sB, long sC, float* __restrict__ csum)
{
    constexpr int MROWS = MTM * 32;
    constexpr int ASZ = (TA == 0) ? MROWS * 20 : 16 * 136;
    constexpr int BSZ = (TB == 0) ? 64 * 20 : 16 * 72;
    __shared__ float Asm[3][ASZ];
    __shared__ float Bsm[3][BSZ];

    int z = blockIdx.z;
    A += (size_t)z * sA; B += (size_t)z * sB; C += (size_t)z * sC;
    int i0 = blockIdx.y * MROWS, j0 = blockIdx.x * 64;
    int tid  = threadIdx.x;
    int warp = tid >> 5, lane = tid & 31, gid = lane >> 2, tig = lane & 3;
    int wr = warp >> 1, wc = warp & 1;

    int nkt = K >> 4;

    auto load_stage = [&](int st, int k0) {
#pragma unroll
        for (int i = 0; i < MROWS / 32; i++) {   // A chunks: MROWS*4 over 128 thr
            int c = tid + i * 128;
            if (TA == 0) { int m = c >> 2, j = (c & 3) << 2;
                cp_async16(&Asm[st][m * 20 + j], A + (size_t)(i0 + m) * lda + k0 + j); }
            else         { int k = c >> 5, m = (c & 31) << 2;
                cp_async16(&Asm[st][k * 136 + m], A + (size_t)(k0 + k) * lda + i0 + m); }
        }
#pragma unroll
        for (int i = 0; i < 2; i++) {
            int c = tid + i * 128;
            if (TB == 0) { int n = c >> 2, j = (c & 3) << 2;
                cp_async16(&Bsm[st][n * 20 + j], B + (size_t)(j0 + n) * ldb + k0 + j); }
            else         { int k = c >> 4, n = (c & 15) << 2;
                cp_async16(&Bsm[st][k * 72 + n], B + (size_t)(k0 + k) * ldb + j0 + n); }
        }
        CP_COMMIT();
    };

    float acc[MTM][4][4] = {};

    load_stage(0, 0);
    if (nkt > 1) load_stage(1, 16);

    for (int kt = 0; kt < nkt; kt++) {
        if (kt + 1 < nkt) asm volatile("cp.async.wait_group 1;");
        else              asm volatile("cp.async.wait_group 0;");
        __syncthreads();

        int cur = kt % 3;
        const unsigned* As = (const unsigned*)Asm[cur];
        const unsigned* Bs = (const unsigned*)Bsm[cur];
#pragma unroll
        for (int ks = 0; ks < 2; ks++) {
            int kk = ks * 8;
            unsigned a[MTM][4], bfr[4][2];
#pragma unroll
            for (int mt = 0; mt < MTM; mt++) {
                int rb = wr * (MTM * 16) + mt * 16;
                if (TA == 0) {
                    a[mt][0] = As[(rb + gid)     * 20 + kk + tig];
                    a[mt][1] = As[(rb + gid + 8) * 20 + kk + tig];
                    a[mt][2] = As[(rb + gid)     * 20 + kk + tig + 4];
                    a[mt][3] = As[(rb + gid + 8) * 20 + kk + tig + 4];
                } else {
                    a[mt][0] = As[(kk + tig)     * 136 + rb + gid];
                    a[mt][1] = As[(kk + tig)     * 136 + rb + gid + 8];
                    a[mt][2] = As[(kk + tig + 4) * 136 + rb + gid];
                    a[mt][3] = As[(kk + tig + 4) * 136 + rb + gid + 8];
                }
            }
#pragma unroll
            for (int nt = 0; nt < 4; nt++) {
                int nb = wc * 32 + nt * 8;
                if (TB == 0) {
                    bfr[nt][0] = Bs[(nb + gid) * 20 + kk + tig];
                    bfr[nt][1] = Bs[(nb + gid) * 20 + kk + tig + 4];
                } else {
                    bfr[nt][0] = Bs[(kk + tig)     * 72 + nb + gid];
                    bfr[nt][1] = Bs[(kk + tig + 4) * 72 + nb + gid];
                }
            }
#pragma unroll
            for (int mt = 0; mt < MTM; mt++)
#pragma unroll
                for (int nt = 0; nt < 4; nt++)
                    mma_tf32(acc[mt][nt], a[mt], bfr[nt]);
        }
        if (kt + 2 < nkt) load_stage((kt + 2) % 3, (kt + 2) << 4);
    }

#pragma unroll
    for (int mt = 0; mt < MTM; mt++) {
        int row0 = i0 + wr * (MTM * 16) + mt * 16 + gid;
#pragma unroll
        for (int nt = 0; nt < 4; nt++) {
            int col0 = j0 + wc * 32 + nt * 8 + 2 * tig;
            float b0 = HASBIAS ? bias[col0]     : 0.f;
            float b1 = HASBIAS ? bias[col0 + 1] : 0.f;
            float v00 = acc[mt][nt][0] + b0, v01 = acc[mt][nt][1] + b1;
            float v10 = acc[mt][nt][2] + b0, v11 = acc[mt][nt][3] + b1;
            if (ROUND) { v00 = round_tf32(v00); v01 = round_tf32(v01);
                         v10 = round_tf32(v10); v11 = round_tf32(v11); }
            C[(size_t)row0 * N + col0]           = v00;
            C[(size_t)row0 * N + col0 + 1]       = v01;
            C[(size_t)(row0 + 8) * N + col0]     = v10;
            C[(size_t)(row0 + 8) * N + col0 + 1] = v11;
        }
    }

    if (SUMEXP) {
#pragma unroll
        for (int nt = 0; nt < 4; nt++) {
            float e0 = 0.f, e1 = 0.f;
#pragma unroll
            for (int mt = 0; mt < MTM; mt++) {
                e0 += __expf(acc[mt][nt][0]) + __expf(acc[mt][nt][2]);
                e1 += __expf(acc[mt][nt][1]) + __expf(acc[mt][nt][3]);
            }
#pragma unroll
            for (int o = 4; o <= 16; o <<= 1) {
                e0 += __shfl_xor_sync(0xffffffffu, e0, o);
                e1 += __shfl_xor_sync(0xffffffffu, e1, o);
            }
            if (gid == 0) {
                int col0 = j0 + wc * 32 + nt * 8 + 2 * tig;
                atomicAdd(&csum[z * Dd + col0],     e0);
                atomicAdd(&csum[z * Dd + col0 + 1], e1);
            }
        }
    }
}

// ============================================================================
// Fused GEMM (C tile ROWS x 256, full output row) + row-LayerNorm epilogue.
//   EPI==0: A-load applies edge-weight transform round(s*exp(s)/csum);
//           E0 = round(LN(C)); out2 = (3+va)*LN(C)       [edge path]
//   EPI==1: A pre-rounded (cp.async); 3-step recurrence -> out1 [node path]
// 2 CTAs/SM.
// ============================================================================
template<int MT, int EPI>
__global__ void __launch_bounds__(256, 2) gemm_ln_kernel(
    const float* __restrict__ A, const float* __restrict__ W,
    const float* __restrict__ g, const float* __restrict__ bt,
    const float* __restrict__ a1,   // EPI0: va   EPI1: ea
    const float* __restrict__ a2,   // EPI1: va
    const float* __restrict__ aux,  // EPI0: csum[Bb*Dd]   EPI1: feat
    float* __restrict__ out1, float* __restrict__ out2)
{
    constexpr int ROWS = MT * 32;
    __shared__ float Asm[2][ROWS * 20];
    __shared__ float Bsm[2][256 * 20];
    __shared__ float invc[EPI == 0 ? 256 : 1];

    int i0 = blockIdx.y * ROWS;
    int tid = threadIdx.x;
    int warp = tid >> 5, lane = tid & 31, gid = lane >> 2, tig = lane & 3;
    int wr = warp >> 2, wc = warp & 3;

    if (EPI == 0) {
        int bidx = i0 / Ee;
        invc[tid] = 1.0f / aux[bidx * Dd + tid];
    }

    auto load_B = [&](int st, int k0) {
#pragma unroll
        for (int i = 0; i < 4; i++) {
            int c = tid + i * 256;
            int n = c >> 2, j = (c & 3) << 2;
            cp_async16(&Bsm[st][n * 20 + j], W + (size_t)n * 256 + k0 + j);
        }
        CP_COMMIT();
    };
    auto load_A_async = [&](int st, int k0) {
#pragma unroll
        for (int i = 0; i < ROWS / 64; i++) {
            int c = tid + i * 256;
            int m = c >> 2, j = (c & 3) << 2;
            cp_async16(&Asm[st][m * 20 + j], A + (size_t)(i0 + m) * 256 + k0 + j);
        }
    };

    float4 ar[ROWS / 64][1];
    int a_m[ROWS / 64], a_j[ROWS / 64];
#pragma unroll
    for (int i = 0; i < ROWS / 64; i++) {
        int c = tid + i * 256;
        a_m[i] = c >> 2; a_j[i] = (c & 3) << 2;
    }
    auto ldg_A = [&](int k0) {
#pragma unroll
        for (int i = 0; i < ROWS / 64; i++)
            ar[i][0] = *(const float4*)(A + (size_t)(i0 + a_m[i]) * 256 + k0 + a_j[i]);
    };
    auto sts_A_transformed = [&](int st, int k0) {
#pragma unroll
        for (int i = 0; i < ROWS / 64; i++) {
            float v[4] = {ar[i][0].x, ar[i][0].y, ar[i][0].z, ar[i][0].w};
            float o[4];
#pragma unroll
            for (int l = 0; l < 4; l++)
                o[l] = round_tf32(v[l] * __expf(v[l]) * invc[k0 + a_j[i] + l]);
            float* d = &Asm[st][a_m[i] * 20 + a_j[i]];
            d[0] = o[0]; d[1] = o[1]; d[2] = o[2]; d[3] = o[3];
        }
    };

    float acc[MT][8][4] = {};

    if (EPI == 0) { ldg_A(0); load_B(0, 0); __syncthreads(); }
    else          { load_A_async(0, 0); load_B(0, 0); }

    for (int kt = 0; kt < 16; kt++) {
        int st = kt & 1;
        if (EPI == 0) {
            asm volatile("cp.async.wait_group 0;");
            sts_A_transformed(st, kt << 4);
            __syncthreads();
            if (kt + 1 < 16) { ldg_A((kt + 1) << 4); load_B(st ^ 1, (kt + 1) << 4); }
        } else {
            asm volatile("cp.async.wait_group 0;");
            __syncthreads();
            if (kt + 1 < 16) { load_A_async(st ^ 1, (kt + 1) << 4); load_B(st ^ 1, (kt + 1) << 4); }
        }
        const unsigned* As = (const unsigned*)Asm[st];
        const unsigned* Bs = (const unsigned*)Bsm[st];
#pragma unroll
        for (int ks = 0; ks < 2; ks++) {
            int kk = ks * 8;
            unsigned a[MT][4], bfr[8][2];
#pragma unroll
            for (int mt = 0; mt < MT; mt++) {
                int rb = wr * (MT * 16) + mt * 16;
                a[mt][0] = As[(rb + gid)     * 20 + kk + tig];
                a[mt][1] = As[(rb + gid + 8) * 20 + kk + tig];
                a[mt][2] = As[(rb + gid)     * 20 + kk + tig + 4];
                a[mt][3] = As[(rb + gid + 8) * 20 + kk + tig + 4];
            }
#pragma unroll
            for (int nt = 0; nt < 8; nt++) {
                int nb = wc * 64 + nt * 8;
                bfr[nt][0] = Bs[(nb + gid) * 20 + kk + tig];
                bfr[nt][1] = Bs[(nb + gid) * 20 + kk + tig + 4];
            }
#pragma unroll
            for (int mt = 0; mt < MT; mt++)
#pragma unroll
                for (int nt = 0; nt < 8; nt++)
                    mma_tf32(acc[mt][nt], a[mt], bfr[nt]);
        }
        if (kt + 1 < 16) __syncthreads();
    }

    __syncthreads();
    float* red  = (float*)Asm;
    float* red2 = red + ROWS * 4;
#pragma unroll
    for (int mt = 0; mt < MT; mt++) {
        float s0 = 0.f, q0 = 0.f, s1 = 0.f, q1 = 0.f;
#pragma unroll
        for (int nt = 0; nt < 8; nt++) {
            const float* c = acc[mt][nt];
            s0 += c[0] + c[1]; q0 += c[0] * c[0] + c[1] * c[1];
            s1 += c[2] + c[3]; q1 += c[2] * c[2] + c[3] * c[3];
        }
#pragma unroll
        for (int o = 1; o <= 2; o <<= 1) {
            s0 += __shfl_xor_sync(0xffffffffu, s0, o);
            q0 += __shfl_xor_sync(0xffffffffu, q0, o);
            s1 += __shfl_xor_sync(0xffffffffu, s1, o);
            q1 += __shfl_xor_sync(0xffffffffu, q1, o);
        }
        if (tig == 0) {
            int r = wr * (MT * 16) + mt * 16 + gid;
            red [r * 4 + wc] = s0;  red2[r * 4 + wc] = q0;
            red [(r + 8) * 4 + wc] = s1;  red2[(r + 8) * 4 + wc] = q1;
        }
    }
    __syncthreads();

    float ea = 0.f, va = 0.f;
    if (EPI == 0) va = *a1;
    else { ea = *a1; va = *a2; }
    float c2 = 3.0f + va;

#pragma unroll
    for (int mt = 0; mt < MT; mt++) {
        int rl0 = wr * (MT * 16) + mt * 16 + gid;
        float mu[2], var[2];
#pragma unroll
        for (int h = 0; h < 2; h++) {
            int rl = rl0 + 8 * h;
            float S  = red [rl * 4] + red [rl * 4 + 1] + red [rl * 4 + 2] + red [rl * 4 + 3];
            float S2 = red2[rl * 4] + red2[rl * 4 + 1] + red2[rl * 4 + 2] + red2[rl * 4 + 3];
            mu[h]  = S * (1.0f / Dd);
            var[h] = S2 * (1.0f / Dd) - mu[h] * mu[h];
        }
        float rsA[2], rsB[2], rsC[2];
#pragma unroll
        for (int h = 0; h < 2; h++) {
            rsA[h] = rsqrtf(var[h] + LNEPS);
            if (EPI == 1) {
                rsB[h] = 2.0f * rsqrtf(4.0f * var[h] + LNEPS);
                rsC[h] = c2 * rsqrtf(c2 * c2 * var[h] + LNEPS);
            }
        }
#pragma unroll
        for (int nt = 0; nt < 8; nt++) {
            int col0 = wc * 64 + nt * 8 + 2 * tig;
            float gg0 = g[col0], gg1 = g[col0 + 1];
            float bb0 = bt[col0], bb1 = bt[col0 + 1];
#pragma unroll
            for (int h = 0; h < 2; h++) {
                size_t ro = (size_t)(i0 + rl0 + 8 * h) * Dd + col0;
                float dx0 = acc[mt][nt][2 * h]     - mu[h];
                float dx1 = acc[mt][nt][2 * h + 1] - mu[h];
                if (EPI == 0) {
                    float y0 = dx0 * rsA[h] * gg0 + bb0;
                    float y1 = dx1 * rsA[h] * gg1 + bb1;
                    out1[ro]     = round_tf32(y0);
                    out1[ro + 1] = round_tf32(y1);
                    out2[ro]     = c2 * y0;
                    out2[ro + 1] = c2 * y1;
                } else {
                    float f0 = aux[ro], f1 = aux[ro + 1];
                    float ya0 = dx0 * rsA[h] * gg0 + bb0, ya1 = dx1 * rsA[h] * gg1 + bb1;
                    float yb0 = dx0 * rsB[h] * gg0 + bb0, yb1 = dx1 * rsB[h] * gg1 + bb1;
                    float yc0 = dx0 * rsC[h] * gg0 + bb0, yc1 = dx1 * rsC[h] * gg1 + bb1;
                    float n0 = (1.0f + ea) * f0 + (1.0f - ea) * ya0;
                    n0 = (1.0f + ea) * n0 + (1.0f - ea) * yb0;
                    n0 = (1.0f + ea) * n0 + (1.0f - ea) * yc0;
                    float n1 = (1.0f + ea) * f1 + (1.0f - ea) * ya1;
                    n1 = (1.0f + ea) * n1 + (1.0f - ea) * yb1;
                    n1 = (1.0f + ea) * n1 + (1.0f - ea) * yc1;
                    out1[ro]     = n0;
                    out1[ro + 1] = n1;
                }
            }
        }
    }
}

// ============================================================================
// tf32 flash attention (R11 shape) + embedded inc->out_inc copy.
// ============================================================================
__global__ void __launch_bounds__(256, 2) attn_tf32_kernel(
    const float* __restrict__ qkv, float* __restrict__ ao,
    const float* __restrict__ inc, float* __restrict__ out_inc)
{
    __shared__ unsigned Qs[64][36];
    __shared__ unsigned Ks[2][64][36];
    __shared__ unsigned Vs[2][64][36];   // [key][d]
    __shared__ unsigned Ps[64][68];      // exp(S) as tf32 bits
    __shared__ float    lrow[64];

    int bh = blockIdx.y; int b = bh >> 3; int h = bh & 7;
    int q0 = blockIdx.x * 64;
    int tid = threadIdx.x;
    int warp = tid >> 5, lane = tid & 31, gid = lane >> 2, tig = lane & 3;
    int wm = warp >> 2, wn = warp & 3;       // S-mma 2x4
    int wm2 = warp >> 1, wn2 = warp & 1;     // PV-mma 4x2
    const float scale = 0.17677669529663687f;

    size_t cbase = ((size_t)bh * gridDim.x + blockIdx.x) * 12288 + (size_t)tid * 4;

    auto load_kv = [&](int st, int kbase) {
#pragma unroll
        for (int i = 0; i < 2; i++) {
            int c = tid + i * 256;
            int m = c >> 3, j = (c & 7) << 2;
            const float* row = qkv + (size_t)(b * Mm + kbase + m) * D3 + h * DHd + j;
            cp_async16(&Ks[st][m][j], row + Dd);
            cp_async16(&Vs[st][m][j], row + 2 * Dd);
        }
        CP_COMMIT();
    };

#pragma unroll
    for (int i = 0; i < 2; i++) {
        int c = tid + i * 256;
        int m = c >> 3, j = (c & 7) << 2;
        cp_async16(&Qs[m][j], qkv + (size_t)(b * Mm + q0 + m) * D3 + h * DHd + j);
    }
    load_kv(0, 0);
    if (tid < 64) lrow[tid] = 0.f;

    float o[2][4] = {};
    int srow = tid >> 2, squad = tid & 3;

    for (int kt = 0; kt < Mm / 64; kt++) {
        int cur = kt & 1;
        asm volatile("cp.async.wait_group 0;");
        __syncthreads();
        if (kt + 1 < Mm / 64) load_kv(cur ^ 1, (kt + 1) * 64);

        float4 cpv;
        bool do_cp = (kt < 12);
        size_t coff = cbase + (size_t)kt * 1024;
        if (do_cp) cpv = *(const float4*)(inc + coff);

        float s[2][2][4] = {};
#pragma unroll
        for (int ks = 0; ks < 4; ks++) {
            int kk = ks * 8;
            unsigned a[2][4], bfr[2][2];
#pragma unroll
            for (int mt = 0; mt < 2; mt++) {
                int rb = wm * 32 + mt * 16;
                a[mt][0] = Qs[rb + gid    ][kk + tig];
                a[mt][1] = Qs[rb + gid + 8][kk + tig];
                a[mt][2] = Qs[rb + gid    ][kk + tig + 4];
                a[mt][3] = Qs[rb + gid + 8][kk + tig + 4];
            }
#pragma unroll
            for (int nt = 0; nt < 2; nt++) {
                int nb = wn * 16 + nt * 8;
                bfr[nt][0] = Ks[cur][nb + gid][kk + tig];
                bfr[nt][1] = Ks[cur][nb + gid][kk + tig + 4];
            }
#pragma unroll
            for (int mt = 0; mt < 2; mt++)
#pragma unroll
                for (int nt = 0; nt < 2; nt++)
                    mma_tf32(s[mt][nt], a[mt], bfr[nt]);
        }

#pragma unroll
        for (int mt = 0; mt < 2; mt++) {
            int r0 = wm * 32 + mt * 16 + gid;
#pragma unroll
            for (int nt = 0; nt < 2; nt++) {
                int c0 = wn * 16 + nt * 8 + 2 * tig;
                Ps[r0    ][c0    ] = f2tf32(__expf(s[mt][nt][0] * scale));
                Ps[r0    ][c0 + 1] = f2tf32(__expf(s[mt][nt][1] * scale));
                Ps[r0 + 8][c0    ] = f2tf32(__expf(s[mt][nt][2] * scale));
                Ps[r0 + 8][c0 + 1] = f2tf32(__expf(s[mt][nt][3] * scale));
            }
        }
        __syncthreads();

        {
            float sm = 0.f;
#pragma unroll
            for (int j = 0; j < 16; j++)
                sm += __uint_as_float(Ps[srow][squad * 16 + j]);
            sm += __shfl_xor_sync(0xffffffffu, sm, 1);
            sm += __shfl_xor_sync(0xffffffffu, sm, 2);
            if (squad == 0) lrow[srow] += sm;
        }

        {
            int rb2 = wm2 * 16;
#pragma unroll
            for (int ks = 0; ks < 8; ks++) {
                int kk = ks * 8;
                unsigned a[4], bfr[2][2];
                a[0] = Ps[rb2 + gid    ][kk + tig];
                a[1] = Ps[rb2 + gid + 8][kk + tig];
                a[2] = Ps[rb2 + gid    ][kk + tig + 4];
                a[3] = Ps[rb2 + gid + 8][kk + tig + 4];
#pragma unroll
                for (int nt = 0; nt < 2; nt++) {
                    int nb = wn2 * 16 + nt * 8;
                    bfr[nt][0] = Vs[cur][kk + tig    ][nb + gid];
                    bfr[nt][1] = Vs[cur][kk + tig + 4][nb + gid];
                }
#pragma unroll
                for (int nt = 0; nt < 2; nt++)
                    mma_tf32(o[nt], a, bfr[nt]);
            }
        }

        if (do_cp) *(float4*)(out_inc + coff) = cpv;
    }
    __syncthreads();

    int r0 = wm2 * 16 + gid;
    float inv0 = 1.0f / lrow[r0];
    float inv8 = 1.0f / lrow[r0 + 8];
#pragma unroll
    for (int nt = 0; nt < 2; nt++) {
        int c0 = wn2 * 16 + nt * 8 + 2 * tig;
        size_t base0 = (size_t)(b * Mm + q0 + r0) * Dd + h * DHd + c0;
        size_t base8 = (size_t)(b * Mm + q0 + r0 + 8) * Dd + h * DHd + c0;
        ao[base0]     = round_tf32(o[nt][0] * inv0);
        ao[base0 + 1] = round_tf32(o[nt][1] * inv0);
        ao[base8]     = round_tf32(o[nt][2] * inv8);
        ao[base8 + 1] = round_tf32(o[nt][3] * inv8);
    }
}

// ============================================================================
extern "C" void kernel_launch(void* const* d_in, const int* in_sizes, int n_in,
                              void* d_out, int out_size) {
    const float* features = (const float*)d_in[0];
    const float* inc      = (const float*)d_in[1];
    const float* vc_Win   = (const float*)d_in[2];
    const float* vc_bin   = (const float*)d_in[3];
    const float* vc_Wout  = (const float*)d_in[4];
    const float* vc_bout  = (const float*)d_in[5];
    const float* vc_Wproj = (const float*)d_in[6];
    const float* vc_ln_g  = (const float*)d_in[7];
    const float* vc_ln_b  = (const float*)d_in[8];
    const float* vc_alpha = (const float*)d_in[9];
    const float* ec_Wproj = (const float*)d_in[14];
    const float* ec_ln_g  = (const float*)d_in[15];
    const float* ec_ln_b  = (const float*)d_in[16];
    const float* ec_alpha = (const float*)d_in[17];

    float* out      = (float*)d_out;
    float* out_node = out;
    float* out_edge = out + (size_t)Bb * Mm * Dd;
    float* out_inc  = out_edge + (size_t)Bb * Ee * Dd;

    float *qkv, *ao, *attn, *S, *E0, *wef, *csum;
    float *featr, *wIn, *wOut, *wPv, *wPe;
    cudaGetSymbolAddress((void**)&qkv,   g_qkv);
    cudaGetSymbolAddress((void**)&ao,    g_ao);
    cudaGetSymbolAddress((void**)&attn,  g_attn);
    cudaGetSymbolAddress((void**)&S,     g_S);
    cudaGetSymbolAddress((void**)&E0,    g_E0);
    cudaGetSymbolAddress((void**)&wef,   g_wef);
    cudaGetSymbolAddress((void**)&csum,  g_csum);
    cudaGetSymbolAddress((void**)&featr, g_featr);
    cudaGetSymbolAddress((void**)&wIn,   g_wIn);
    cudaGetSymbolAddress((void**)&wOut,  g_wOut);
    cudaGetSymbolAddress((void**)&wPv,   g_wPv);
    cudaGetSymbolAddress((void**)&wPe,   g_wPe);

    // 0) pre-round all GEMM operands + zero csum (one kernel)
    {
        size_t tot = (size_t)Bb * Mm * Dd + (size_t)D3 * Dd + 3 * (size_t)Dd * Dd
                   + (size_t)Bb * Dd;
        round_all_kernel<<<(int)((tot + 255) / 256), 256>>>(
            features, vc_Win, vc_Wout, vc_Wproj, ec_Wproj,
            featr, wIn, wOut, wPv, wPe, csum);
    }

    // 1) QKV = features @ vc_Win^T + vc_bin  (ROUNDED: attention reads raw bits)
    gemm_tf32_kernel<4, 0, 0, true, true, false><<<dim3(D3 / 64, (Bb * Mm) / 128, 1), 128>>>(
        featr, wIn, vc_bin, qkv, Bb * Mm, D3, Dd, Dd, Dd, 0, 0, 0, nullptr);

    // 2) flash attention -> ao (rounded) + embedded inc passthrough copy
    attn_tf32_kernel<<<dim3(Mm / 64, Bb * Hh), 256>>>(qkv, ao, inc, out_inc);

    // 3) attn = ao @ vc_Wout^T + vc_bout (rounded) — 64x64 tiles, grid 512
    gemm_tf32_kernel<2, 0, 0, true, true, false><<<dim3(Dd / 64, (Bb * Mm) / 64, 1), 128>>>(
        ao, wOut, vc_bout, attn, Bb * Mm, Dd, Dd, Dd, Dd, 0, 0, 0, nullptr);

    // 4) S[b,e,d] = sum_m inc[b,m,e] * attn[b,m,d]  + fused exp column sums
    gemm_tf32_kernel<4, 1, 1, false, false, true><<<dim3(Dd / 64, Ee / 128, Bb), 128>>>(
        inc, attn, nullptr, S, Ee, Dd, Mm, Ee, Dd,
        (long)Mm * Ee, (long)Mm * Dd, (long)Ee * Dd, csum);

    // 6+7) fused: edge-weight transform + (edge @ vc_Wproj^T) -> LN -> E0 + out_edge
    gemm_ln_kernel<2, 0><<<dim3(1, (Bb * Ee) / 64), 256>>>(
        S, wPv, vc_ln_g, vc_ln_b, vc_alpha, nullptr, csum, E0, out_edge);

    // 8) wef = inc @ E0 (rounded) — 64x64 tiles, grid 512
    gemm_tf32_kernel<2, 0, 1, false, true, false><<<dim3(Dd / 64, Mm / 64, Bb), 128>>>(
        inc, E0, nullptr, wef, Mm, Dd, Ee, Ee, Dd,
        (long)Mm * Ee, (long)Ee * Dd, (long)Mm * Dd, nullptr);

    // 9) fused: (wef @ ec_Wproj^T) -> LN -> 3-step recurrence -> out_node
    gemm_ln_kernel<2, 1><<<dim3(1, (Bb * Mm) / 64), 256>>>(
        wef, wPe, ec_ln_g, ec_ln_b, ec_alpha, vc_alpha, features, out_node, nullptr);
}

// round 14
// speedup vs baseline: 1.0295x; 1.0295x over previous
#include <cuda_runtime.h>
#include <math.h>

#define Bb 8
#define Mm 1024
#define Ee 1536
#define Dd 256
#define Hh 8
#define DHd 32
#define D3 768
#define LNEPS 1e-5f

// -------------------- scratch (static __device__, no allocation) -----------
__device__ float g_qkv  [Bb*Mm*D3];
__device__ float g_ao   [Bb*Mm*Dd];
__device__ float g_attn [Bb*Mm*Dd];
__device__ float g_S    [Bb*Ee*Dd];
__device__ float g_E0   [Bb*Ee*Dd];
__device__ float g_wef  [Bb*Mm*Dd];
__device__ float g_csum [Bb*Dd];
__device__ float g_wIn  [D3*Dd];
__device__ float g_wOut [Dd*Dd];
__device__ float g_wPv  [Dd*Dd];
__device__ float g_wPe  [Dd*Dd];

// -------------------- tf32 / async helpers ----------------------------------
__device__ __forceinline__ unsigned f2tf32(float x) {
    unsigned r;
    asm("cvt.rna.tf32.f32 %0, %1;" : "=r"(r) : "f"(x));
    return r;
}
__device__ __forceinline__ float round_tf32(float x) {
    return __uint_as_float(f2tf32(x));
}

__device__ __forceinline__ void mma_tf32(float c[4], const unsigned a[4], const unsigned b[2]) {
    asm volatile(
        "mma.sync.aligned.m16n8k8.row.col.f32.tf32.tf32.f32 "
        "{%0,%1,%2,%3}, {%4,%5,%6,%7}, {%8,%9}, {%0,%1,%2,%3};"
        : "+f"(c[0]), "+f"(c[1]), "+f"(c[2]), "+f"(c[3])
        : "r"(a[0]), "r"(a[1]), "r"(a[2]), "r"(a[3]), "r"(b[0]), "r"(b[1]));
}

__device__ __forceinline__ void cp_async16(void* smem_dst, const float* gsrc) {
    unsigned s = (unsigned)__cvta_generic_to_shared(smem_dst);
    asm volatile("cp.async.ca.shared.global [%0], [%1], 16;" :: "r"(s), "l"(gsrc));
}
#define CP_COMMIT() asm volatile("cp.async.commit_group;")

// -------------------- weight pre-round kernel (+ csum zero tail) ------------
__global__ void round_all_kernel(const float* __restrict__ w1, const float* __restrict__ w2,
                                 const float* __restrict__ w3, const float* __restrict__ w4,
                                 float* __restrict__ o1, float* __restrict__ o2,
                                 float* __restrict__ o3, float* __restrict__ o4,
                                 float* __restrict__ csum) {
    const size_t N1 = (size_t)D3 * Dd, N2 = (size_t)Dd * Dd;
    size_t i = (size_t)blockIdx.x * 256 + threadIdx.x;
    if (i < N1) { o1[i] = round_tf32(w1[i]); return; }
    i -= N1;
    if (i < N2) { o2[i] = round_tf32(w2[i]); return; }
    i -= N2;
    if (i < N2) { o3[i] = round_tf32(w3[i]); return; }
    i -= N2;
    if (i < N2) { o4[i] = round_tf32(w4[i]); return; }
    i -= N2;
    if (i < (size_t)Bb * Dd) csum[i] = 0.f;
}

// ============================================================================
// tf32 GEMM, cp.async 3-stage ring (R12 tiling: 128x64x16, 4 warps, 64x32
// warp tiles, 3 CTAs/SM).
//   TA==0: A stored [M,K]   TA==1: A stored [K,M]
//   TB==0: B stored [N,K]   TB==1: B stored [K,N]
//   CVTA: apply tf32 rounding to A fragments at read (A may be raw fp32).
//   SUMEXP: epilogue column-sums exp(acc) into csum[z*Dd + col] (atomic).
// ============================================================================
template<int TA, int TB, bool HASBIAS, bool ROUND, bool SUMEXP, bool CVTA>
__global__ void __launch_bounds__(128, 3) gemm_tf32_kernel(
    const float* __restrict__ A, const float* __restrict__ B,
    const float* __restrict__ bias, float* __restrict__ C,
    int M, int N, int K, int lda, int ldb,
    long sA, long sB, long sC, float* __restrict__ csum)
{
    constexpr int ASZ = (TA == 0) ? 128 * 20 : 16 * 136;
    constexpr int BSZ = (TB == 0) ? 64 * 20 : 16 * 72;
    __shared__ float Asm[3][ASZ];
    __shared__ float Bsm[3][BSZ];

    int z = blockIdx.z;
    A += (size_t)z * sA; B += (size_t)z * sB; C += (size_t)z * sC;
    int i0 = blockIdx.y * 128, j0 = blockIdx.x * 64;
    int tid  = threadIdx.x;
    int warp = tid >> 5, lane = tid & 31, gid = lane >> 2, tig = lane & 3;
    int wr = warp >> 1, wc = warp & 1;

    int nkt = K >> 4;

    auto load_stage = [&](int st, int k0) {
#pragma unroll
        for (int i = 0; i < 4; i++) {
            int c = tid + i * 128;
            if (TA == 0) { int m = c >> 2, j = (c & 3) << 2;
                cp_async16(&Asm[st][m * 20 + j], A + (size_t)(i0 + m) * lda + k0 + j); }
            else         { int k = c >> 5, m = (c & 31) << 2;
                cp_async16(&Asm[st][k * 136 + m], A + (size_t)(k0 + k) * lda + i0 + m); }
        }
#pragma unroll
        for (int i = 0; i < 2; i++) {
            int c = tid + i * 128;
            if (TB == 0) { int n = c >> 2, j = (c & 3) << 2;
                cp_async16(&Bsm[st][n * 20 + j], B + (size_t)(j0 + n) * ldb + k0 + j); }
            else         { int k = c >> 4, n = (c & 15) << 2;
                cp_async16(&Bsm[st][k * 72 + n], B + (size_t)(k0 + k) * ldb + j0 + n); }
        }
        CP_COMMIT();
    };

    auto afrag = [&](unsigned raw) -> unsigned {
        return CVTA ? f2tf32(__uint_as_float(raw)) : raw;
    };

    float acc[4][4][4] = {};

    load_stage(0, 0);
    if (nkt > 1) load_stage(1, 16);

    for (int kt = 0; kt < nkt; kt++) {
        if (kt + 1 < nkt) asm volatile("cp.async.wait_group 1;");
        else              asm volatile("cp.async.wait_group 0;");
        __syncthreads();

        int cur = kt % 3;
        const unsigned* As = (const unsigned*)Asm[cur];
        const unsigned* Bs = (const unsigned*)Bsm[cur];
#pragma unroll
        for (int ks = 0; ks < 2; ks++) {
            int kk = ks * 8;
            unsigned a[4][4], bfr[4][2];
#pragma unroll
            for (int mt = 0; mt < 4; mt++) {
                int rb = wr * 64 + mt * 16;
                if (TA == 0) {
                    a[mt][0] = afrag(As[(rb + gid)     * 20 + kk + tig]);
                    a[mt][1] = afrag(As[(rb + gid + 8) * 20 + kk + tig]);
                    a[mt][2] = afrag(As[(rb + gid)     * 20 + kk + tig + 4]);
                    a[mt][3] = afrag(As[(rb + gid + 8) * 20 + kk + tig + 4]);
                } else {
                    a[mt][0] = As[(kk + tig)     * 136 + rb + gid];
                    a[mt][1] = As[(kk + tig)     * 136 + rb + gid + 8];
                    a[mt][2] = As[(kk + tig + 4) * 136 + rb + gid];
                    a[mt][3] = As[(kk + tig + 4) * 136 + rb + gid + 8];
                }
            }
#pragma unroll
            for (int nt = 0; nt < 4; nt++) {
                int nb = wc * 32 + nt * 8;
                if (TB == 0) {
                    bfr[nt][0] = Bs[(nb + gid) * 20 + kk + tig];
                    bfr[nt][1] = Bs[(nb + gid) * 20 + kk + tig + 4];
                } else {
                    bfr[nt][0] = Bs[(kk + tig)     * 72 + nb + gid];
                    bfr[nt][1] = Bs[(kk + tig + 4) * 72 + nb + gid];
                }
            }
#pragma unroll
            for (int mt = 0; mt < 4; mt++)
#pragma unroll
                for (int nt = 0; nt < 4; nt++)
                    mma_tf32(acc[mt][nt], a[mt], bfr[nt]);
        }
        if (kt + 2 < nkt) load_stage((kt + 2) % 3, (kt + 2) << 4);
    }

#pragma unroll
    for (int mt = 0; mt < 4; mt++) {
        int row0 = i0 + wr * 64 + mt * 16 + gid;
#pragma unroll
        for (int nt = 0; nt < 4; nt++) {
            int col0 = j0 + wc * 32 + nt * 8 + 2 * tig;
            float b0 = HASBIAS ? bias[col0]     : 0.f;
            float b1 = HASBIAS ? bias[col0 + 1] : 0.f;
            float v00 = acc[mt][nt][0] + b0, v01 = acc[mt][nt][1] + b1;
            float v10 = acc[mt][nt][2] + b0, v11 = acc[mt][nt][3] + b1;
            if (ROUND) { v00 = round_tf32(v00); v01 = round_tf32(v01);
                         v10 = round_tf32(v10); v11 = round_tf32(v11); }
            C[(size_t)row0 * N + col0]           = v00;
            C[(size_t)row0 * N + col0 + 1]       = v01;
            C[(size_t)(row0 + 8) * N + col0]     = v10;
            C[(size_t)(row0 + 8) * N + col0 + 1] = v11;
        }
    }

    if (SUMEXP) {
#pragma unroll
        for (int nt = 0; nt < 4; nt++) {
            float e0 = 0.f, e1 = 0.f;
#pragma unroll
            for (int mt = 0; mt < 4; mt++) {
                e0 += __expf(acc[mt][nt][0]) + __expf(acc[mt][nt][2]);
                e1 += __expf(acc[mt][nt][1]) + __expf(acc[mt][nt][3]);
            }
#pragma unroll
            for (int o = 4; o <= 16; o <<= 1) {
                e0 += __shfl_xor_sync(0xffffffffu, e0, o);
                e1 += __shfl_xor_sync(0xffffffffu, e1, o);
            }
            if (gid == 0) {
                int col0 = j0 + wc * 32 + nt * 8 + 2 * tig;
                atomicAdd(&csum[z * Dd + col0],     e0);
                atomicAdd(&csum[z * Dd + col0 + 1], e1);
            }
        }
    }
}

// ============================================================================
// Fused GEMM (C tile ROWS x 256, full output row) + row-LayerNorm epilogue.
//   EPI==0: A-load applies edge-weight transform round(s*exp(s)/csum);
//           E0 = round(LN(C)); out2 = (3+va)*LN(C)       [edge path]
//   EPI==1: A pre-rounded (cp.async); 3-step recurrence -> out1 [node path]
// 2 CTAs/SM.
// ============================================================================
template<int MT, int EPI>
__global__ void __launch_bounds__(256, 2) gemm_ln_kernel(
    const float* __restrict__ A, const float* __restrict__ W,
    const float* __restrict__ g, const float* __restrict__ bt,
    const float* __restrict__ a1,   // EPI0: va   EPI1: ea
    const float* __restrict__ a2,   // EPI1: va
    const float* __restrict__ aux,  // EPI0: csum[Bb*Dd]   EPI1: feat
    float* __restrict__ out1, float* __restrict__ out2)
{
    constexpr int ROWS = MT * 32;
    __shared__ float Asm[2][ROWS * 20];
    __shared__ float Bsm[2][256 * 20];
    __shared__ float invc[EPI == 0 ? 256 : 1];

    int i0 = blockIdx.y * ROWS;
    int tid = threadIdx.x;
    int warp = tid >> 5, lane = tid & 31, gid = lane >> 2, tig = lane & 3;
    int wr = warp >> 2, wc = warp & 3;

    if (EPI == 0) {
        int bidx = i0 / Ee;
        invc[tid] = 1.0f / aux[bidx * Dd + tid];
    }

    auto load_B = [&](int st, int k0) {
#pragma unroll
        for (int i = 0; i < 4; i++) {
            int c = tid + i * 256;
            int n = c >> 2, j = (c & 3) << 2;
            cp_async16(&Bsm[st][n * 20 + j], W + (size_t)n * 256 + k0 + j);
        }
        CP_COMMIT();
    };
    auto load_A_async = [&](int st, int k0) {
#pragma unroll
        for (int i = 0; i < ROWS / 64; i++) {
            int c = tid + i * 256;
            int m = c >> 2, j = (c & 3) << 2;
            cp_async16(&Asm[st][m * 20 + j], A + (size_t)(i0 + m) * 256 + k0 + j);
        }
    };

    float4 ar[ROWS / 64][1];
    int a_m[ROWS / 64], a_j[ROWS / 64];
#pragma unroll
    for (int i = 0; i < ROWS / 64; i++) {
        int c = tid + i * 256;
        a_m[i] = c >> 2; a_j[i] = (c & 3) << 2;
    }
    auto ldg_A = [&](int k0) {
#pragma unroll
        for (int i = 0; i < ROWS / 64; i++)
            ar[i][0] = *(const float4*)(A + (size_t)(i0 + a_m[i]) * 256 + k0 + a_j[i]);
    };
    auto sts_A_transformed = [&](int st, int k0) {
#pragma unroll
        for (int i = 0; i < ROWS / 64; i++) {
            float v[4] = {ar[i][0].x, ar[i][0].y, ar[i][0].z, ar[i][0].w};
            float o[4];
#pragma unroll
            for (int l = 0; l < 4; l++)
                o[l] = round_tf32(v[l] * __expf(v[l]) * invc[k0 + a_j[i] + l]);
            float* d = &Asm[st][a_m[i] * 20 + a_j[i]];
            d[0] = o[0]; d[1] = o[1]; d[2] = o[2]; d[3] = o[3];
        }
    };

    float acc[MT][8][4] = {};

    if (EPI == 0) { ldg_A(0); load_B(0, 0); __syncthreads(); }
    else          { load_A_async(0, 0); load_B(0, 0); }

    for (int kt = 0; kt < 16; kt++) {
        int st = kt & 1;
        if (EPI == 0) {
            asm volatile("cp.async.wait_group 0;");
            sts_A_transformed(st, kt << 4);
            __syncthreads();
            if (kt + 1 < 16) { ldg_A((kt + 1) << 4); load_B(st ^ 1, (kt + 1) << 4); }
        } else {
            asm volatile("cp.async.wait_group 0;");
            __syncthreads();
            if (kt + 1 < 16) { load_A_async(st ^ 1, (kt + 1) << 4); load_B(st ^ 1, (kt + 1) << 4); }
        }
        const unsigned* As = (const unsigned*)Asm[st];
        const unsigned* Bs = (const unsigned*)Bsm[st];
#pragma unroll
        for (int ks = 0; ks < 2; ks++) {
            int kk = ks * 8;
            unsigned a[MT][4], bfr[8][2];
#pragma unroll
            for (int mt = 0; mt < MT; mt++) {
                int rb = wr * (MT * 16) + mt * 16;
                a[mt][0] = As[(rb + gid)     * 20 + kk + tig];
                a[mt][1] = As[(rb + gid + 8) * 20 + kk + tig];
                a[mt][2] = As[(rb + gid)     * 20 + kk + tig + 4];
                a[mt][3] = As[(rb + gid + 8) * 20 + kk + tig + 4];
            }
#pragma unroll
            for (int nt = 0; nt < 8; nt++) {
                int nb = wc * 64 + nt * 8;
                bfr[nt][0] = Bs[(nb + gid) * 20 + kk + tig];
                bfr[nt][1] = Bs[(nb + gid) * 20 + kk + tig + 4];
            }
#pragma unroll
            for (int mt = 0; mt < MT; mt++)
#pragma unroll
                for (int nt = 0; nt < 8; nt++)
                    mma_tf32(acc[mt][nt], a[mt], bfr[nt]);
        }
        if (kt + 1 < 16) __syncthreads();
    }

    __syncthreads();
    float* red  = (float*)Asm;
    float* red2 = red + ROWS * 4;
#pragma unroll
    for (int mt = 0; mt < MT; mt++) {
        float s0 = 0.f, q0 = 0.f, s1 = 0.f, q1 = 0.f;
#pragma unroll
        for (int nt = 0; nt < 8; nt++) {
            const float* c = acc[mt][nt];
            s0 += c[0] + c[1]; q0 += c[0] * c[0] + c[1] * c[1];
            s1 += c[2] + c[3]; q1 += c[2] * c[2] + c[3] * c[3];
        }
#pragma unroll
        for (int o = 1; o <= 2; o <<= 1) {
            s0 += __shfl_xor_sync(0xffffffffu, s0, o);
            q0 += __shfl_xor_sync(0xffffffffu, q0, o);
            s1 += __shfl_xor_sync(0xffffffffu, s1, o);
            q1 += __shfl_xor_sync(0xffffffffu, q1, o);
        }
        if (tig == 0) {
            int r = wr * (MT * 16) + mt * 16 + gid;
            red [r * 4 + wc] = s0;  red2[r * 4 + wc] = q0;
            red [(r + 8) * 4 + wc] = s1;  red2[(r + 8) * 4 + wc] = q1;
        }
    }
    __syncthreads();

    float ea = 0.f, va = 0.f;
    if (EPI == 0) va = *a1;
    else { ea = *a1; va = *a2; }
    float c2 = 3.0f + va;

#pragma unroll
    for (int mt = 0; mt < MT; mt++) {
        int rl0 = wr * (MT * 16) + mt * 16 + gid;
        float mu[2], var[2];
#pragma unroll
        for (int h = 0; h < 2; h++) {
            int rl = rl0 + 8 * h;
            float S  = red [rl * 4] + red [rl * 4 + 1] + red [rl * 4 + 2] + red [rl * 4 + 3];
            float S2 = red2[rl * 4] + red2[rl * 4 + 1] + red2[rl * 4 + 2] + red2[rl * 4 + 3];
            mu[h]  = S * (1.0f / Dd);
            var[h] = S2 * (1.0f / Dd) - mu[h] * mu[h];
        }
        float rsA[2], rsB[2], rsC[2];
#pragma unroll
        for (int h = 0; h < 2; h++) {
            rsA[h] = rsqrtf(var[h] + LNEPS);
            if (EPI == 1) {
                rsB[h] = 2.0f * rsqrtf(4.0f * var[h] + LNEPS);
                rsC[h] = c2 * rsqrtf(c2 * c2 * var[h] + LNEPS);
            }
        }
#pragma unroll
        for (int nt = 0; nt < 8; nt++) {
            int col0 = wc * 64 + nt * 8 + 2 * tig;
            float gg0 = g[col0], gg1 = g[col0 + 1];
            float bb0 = bt[col0], bb1 = bt[col0 + 1];
#pragma unroll
            for (int h = 0; h < 2; h++) {
                size_t ro = (size_t)(i0 + rl0 + 8 * h) * Dd + col0;
                float dx0 = acc[mt][nt][2 * h]     - mu[h];
                float dx1 = acc[mt][nt][2 * h + 1] - mu[h];
                if (EPI == 0) {
                    float y0 = dx0 * rsA[h] * gg0 + bb0;
                    float y1 = dx1 * rsA[h] * gg1 + bb1;
                    out1[ro]     = round_tf32(y0);
                    out1[ro + 1] = round_tf32(y1);
                    out2[ro]     = c2 * y0;
                    out2[ro + 1] = c2 * y1;
                } else {
                    float f0 = aux[ro], f1 = aux[ro + 1];
                    float ya0 = dx0 * rsA[h] * gg0 + bb0, ya1 = dx1 * rsA[h] * gg1 + bb1;
                    float yb0 = dx0 * rsB[h] * gg0 + bb0, yb1 = dx1 * rsB[h] * gg1 + bb1;
                    float yc0 = dx0 * rsC[h] * gg0 + bb0, yc1 = dx1 * rsC[h] * gg1 + bb1;
                    float n0 = (1.0f + ea) * f0 + (1.0f - ea) * ya0;
                    n0 = (1.0f + ea) * n0 + (1.0f - ea) * yb0;
                    n0 = (1.0f + ea) * n0 + (1.0f - ea) * yc0;
                    float n1 = (1.0f + ea) * f1 + (1.0f - ea) * ya1;
                    n1 = (1.0f + ea) * n1 + (1.0f - ea) * yb1;
                    n1 = (1.0f + ea) * n1 + (1.0f - ea) * yc1;
                    out1[ro]     = n0;
                    out1[ro + 1] = n1;
                }
            }
        }
    }
}

// ============================================================================
// tf32 flash attention (R11 shape) + embedded inc->out_inc copy.
// ============================================================================
__global__ void __launch_bounds__(256, 2) attn_tf32_kernel(
    const float* __restrict__ qkv, float* __restrict__ ao,
    const float* __restrict__ inc, float* __restrict__ out_inc)
{
    __shared__ unsigned Qs[64][36];
    __shared__ unsigned Ks[2][64][36];
    __shared__ unsigned Vs[2][64][36];   // [key][d]
    __shared__ unsigned Ps[64][68];      // exp(S) as tf32 bits
    __shared__ float    lrow[64];

    int bh = blockIdx.y; int b = bh >> 3; int h = bh & 7;
    int q0 = blockIdx.x * 64;
    int tid = threadIdx.x;
    int warp = tid >> 5, lane = tid & 31, gid = lane >> 2, tig = lane & 3;
    int wm = warp >> 2, wn = warp & 3;       // S-mma 2x4
    int wm2 = warp >> 1, wn2 = warp & 1;     // PV-mma 4x2
    const float scale = 0.17677669529663687f;

    size_t cbase = ((size_t)bh * gridDim.x + blockIdx.x) * 12288 + (size_t)tid * 4;

    auto load_kv = [&](int st, int kbase) {
#pragma unroll
        for (int i = 0; i < 2; i++) {
            int c = tid + i * 256;
            int m = c >> 3, j = (c & 7) << 2;
            const float* row = qkv + (size_t)(b * Mm + kbase + m) * D3 + h * DHd + j;
            cp_async16(&Ks[st][m][j], row + Dd);
            cp_async16(&Vs[st][m][j], row + 2 * Dd);
        }
        CP_COMMIT();
    };

#pragma unroll
    for (int i = 0; i < 2; i++) {
        int c = tid + i * 256;
        int m = c >> 3, j = (c & 7) << 2;
        cp_async16(&Qs[m][j], qkv + (size_t)(b * Mm + q0 + m) * D3 + h * DHd + j);
    }
    load_kv(0, 0);
    if (tid < 64) lrow[tid] = 0.f;

    float o[2][4] = {};
    int srow = tid >> 2, squad = tid & 3;

    for (int kt = 0; kt < Mm / 64; kt++) {
        int cur = kt & 1;
        asm volatile("cp.async.wait_group 0;");
        __syncthreads();
        if (kt + 1 < Mm / 64) load_kv(cur ^ 1, (kt + 1) * 64);

        float4 cpv;
        bool do_cp = (kt < 12);
        size_t coff = cbase + (size_t)kt * 1024;
        if (do_cp) cpv = *(const float4*)(inc + coff);

        float s[2][2][4] = {};
#pragma unroll
        for (int ks = 0; ks < 4; ks++) {
            int kk = ks * 8;
            unsigned a[2][4], bfr[2][2];
#pragma unroll
            for (int mt = 0; mt < 2; mt++) {
                int rb = wm * 32 + mt * 16;
                a[mt][0] = Qs[rb + gid    ][kk + tig];
                a[mt][1] = Qs[rb + gid + 8][kk + tig];
                a[mt][2] = Qs[rb + gid    ][kk + tig + 4];
                a[mt][3] = Qs[rb + gid + 8][kk + tig + 4];
            }
#pragma unroll
            for (int nt = 0; nt < 2; nt++) {
                int nb = wn * 16 + nt * 8;
                bfr[nt][0] = Ks[cur][nb + gid][kk + tig];
                bfr[nt][1] = Ks[cur][nb + gid][kk + tig + 4];
            }
#pragma unroll
            for (int mt = 0; mt < 2; mt++)
#pragma unroll
                for (int nt = 0; nt < 2; nt++)
                    mma_tf32(s[mt][nt], a[mt], bfr[nt]);
        }

#pragma unroll
        for (int mt = 0; mt < 2; mt++) {
            int r0 = wm * 32 + mt * 16 + gid;
#pragma unroll
            for (int nt = 0; nt < 2; nt++) {
                int c0 = wn * 16 + nt * 8 + 2 * tig;
                Ps[r0    ][c0    ] = f2tf32(__expf(s[mt][nt][0] * scale));
                Ps[r0    ][c0 + 1] = f2tf32(__expf(s[mt][nt][1] * scale));
                Ps[r0 + 8][c0    ] = f2tf32(__expf(s[mt][nt][2] * scale));
                Ps[r0 + 8][c0 + 1] = f2tf32(__expf(s[mt][nt][3] * scale));
            }
        }
        __syncthreads();

        {
            float sm = 0.f;
#pragma unroll
            for (int j = 0; j < 16; j++)
                sm += __uint_as_float(Ps[srow][squad * 16 + j]);
            sm += __shfl_xor_sync(0xffffffffu, sm, 1);
            sm += __shfl_xor_sync(0xffffffffu, sm, 2);
            if (squad == 0) lrow[srow] += sm;
        }

        {
            int rb2 = wm2 * 16;
#pragma unroll
            for (int ks = 0; ks < 8; ks++) {
                int kk = ks * 8;
                unsigned a[4], bfr[2][2];
                a[0] = Ps[rb2 + gid    ][kk + tig];
                a[1] = Ps[rb2 + gid + 8][kk + tig];
                a[2] = Ps[rb2 + gid    ][kk + tig + 4];
                a[3] = Ps[rb2 + gid + 8][kk + tig + 4];
#pragma unroll
                for (int nt = 0; nt < 2; nt++) {
                    int nb = wn2 * 16 + nt * 8;
                    bfr[nt][0] = Vs[cur][kk + tig    ][nb + gid];
                    bfr[nt][1] = Vs[cur][kk + tig + 4][nb + gid];
                }
#pragma unroll
                for (int nt = 0; nt < 2; nt++)
                    mma_tf32(o[nt], a, bfr[nt]);
            }
        }

        if (do_cp) *(float4*)(out_inc + coff) = cpv;
    }
    __syncthreads();

    int r0 = wm2 * 16 + gid;
    float inv0 = 1.0f / lrow[r0];
    float inv8 = 1.0f / lrow[r0 + 8];
#pragma unroll
    for (int nt = 0; nt < 2; nt++) {
        int c0 = wn2 * 16 + nt * 8 + 2 * tig;
        size_t base0 = (size_t)(b * Mm + q0 + r0) * Dd + h * DHd + c0;
        size_t base8 = (size_t)(b * Mm + q0 + r0 + 8) * Dd + h * DHd + c0;
        ao[base0]     = round_tf32(o[nt][0] * inv0);
        ao[base0 + 1] = round_tf32(o[nt][1] * inv0);
        ao[base8]     = round_tf32(o[nt][2] * inv8);
        ao[base8 + 1] = round_tf32(o[nt][3] * inv8);
    }
}

// ============================================================================
extern "C" void kernel_launch(void* const* d_in, const int* in_sizes, int n_in,
                              void* d_out, int out_size) {
    const float* features = (const float*)d_in[0];
    const float* inc      = (const float*)d_in[1];
    const float* vc_Win   = (const float*)d_in[2];
    const float* vc_bin   = (const float*)d_in[3];
    const float* vc_Wout  = (const float*)d_in[4];
    const float* vc_bout  = (const float*)d_in[5];
    const float* vc_Wproj = (const float*)d_in[6];
    const float* vc_ln_g  = (const float*)d_in[7];
    const float* vc_ln_b  = (const float*)d_in[8];
    const float* vc_alpha = (const float*)d_in[9];
    const float* ec_Wproj = (const float*)d_in[14];
    const float* ec_ln_g  = (const float*)d_in[15];
    const float* ec_ln_b  = (const float*)d_in[16];
    const float* ec_alpha = (const float*)d_in[17];

    float* out      = (float*)d_out;
    float* out_node = out;
    float* out_edge = out + (size_t)Bb * Mm * Dd;
    float* out_inc  = out_edge + (size_t)Bb * Ee * Dd;

    float *qkv, *ao, *attn, *S, *E0, *wef, *csum;
    float *wIn, *wOut, *wPv, *wPe;
    cudaGetSymbolAddress((void**)&qkv,   g_qkv);
    cudaGetSymbolAddress((void**)&ao,    g_ao);
    cudaGetSymbolAddress((void**)&attn,  g_attn);
    cudaGetSymbolAddress((void**)&S,     g_S);
    cudaGetSymbolAddress((void**)&E0,    g_E0);
    cudaGetSymbolAddress((void**)&wef,   g_wef);
    cudaGetSymbolAddress((void**)&csum,  g_csum);
    cudaGetSymbolAddress((void**)&wIn,   g_wIn);
    cudaGetSymbolAddress((void**)&wOut,  g_wOut);
    cudaGetSymbolAddress((void**)&wPv,   g_wPv);
    cudaGetSymbolAddress((void**)&wPe,   g_wPe);

    // 0) pre-round weight operands + zero csum (one small kernel)
    {
        size_t tot = (size_t)D3 * Dd + 3 * (size_t)Dd * Dd + (size_t)Bb * Dd;
        round_all_kernel<<<(int)((tot + 255) / 256), 256>>>(
            vc_Win, vc_Wout, vc_Wproj, ec_Wproj,
            wIn, wOut, wPv, wPe, csum);
    }

    // 1) QKV = features @ vc_Win^T + vc_bin  (A rounded at fragment read)
    gemm_tf32_kernel<0, 0, true, true, false, true><<<dim3(D3 / 64, (Bb * Mm) / 128, 1), 128>>>(
        features, wIn, vc_bin, qkv, Bb * Mm, D3, Dd, Dd, Dd, 0, 0, 0, nullptr);

    // 2) flash attention -> ao (rounded) + embedded inc passthrough copy
    attn_tf32_kernel<<<dim3(Mm / 64, Bb * Hh), 256>>>(qkv, ao, inc, out_inc);

    // 3) attn = ao @ vc_Wout^T + vc_bout (rounded)
    gemm_tf32_kernel<0, 0, true, true, false, false><<<dim3(Dd / 64, (Bb * Mm) / 128, 1), 128>>>(
        ao, wOut, vc_bout, attn, Bb * Mm, Dd, Dd, Dd, Dd, 0, 0, 0, nullptr);

    // 4) S[b,e,d] = sum_m inc[b,m,e] * attn[b,m,d]  + fused exp column sums
    gemm_tf32_kernel<1, 1, false, false, true, false><<<dim3(Dd / 64, Ee / 128, Bb), 128>>>(
        inc, attn, nullptr, S, Ee, Dd, Mm, Ee, Dd,
        (long)Mm * Ee, (long)Mm * Dd, (long)Ee * Dd, csum);

    // 6+7) fused: edge-weight transform + (edge @ vc_Wproj^T) -> LN -> E0 + out_edge
    gemm_ln_kernel<2, 0><<<dim3(1, (Bb * Ee) / 64), 256>>>(
        S, wPv, vc_ln_g, vc_ln_b, vc_alpha, nullptr, csum, E0, out_edge);

    // 8) wef = inc @ E0 (rounded)
    gemm_tf32_kernel<0, 1, false, true, false, false><<<dim3(Dd / 64, Mm / 128, Bb), 128>>>(
        inc, E0, nullptr, wef, Mm, Dd, Ee, Ee, Dd,
        (long)Mm * Ee, (long)Ee * Dd, (long)Mm * Dd, nullptr);

    // 9) fused: (wef @ ec_Wproj^T) -> LN -> 3-step recurrence -> out_node
    gemm_ln_kernel<2, 1><<<dim3(1, (Bb * Mm) / 64), 256>>>(
        wef, wPe, ec_ln_g, ec_ln_b, ec_alpha, vc_alpha, features, out_node, nullptr);
}

// round 15
// speedup vs baseline: 1.0367x; 1.0070x over previous
#include <cuda_runtime.h>
#include <math.h>

#define Bb 8
#define Mm 1024
#define Ee 1536
#define Dd 256
#define Hh 8
#define DHd 32
#define D3 768
#define LNEPS 1e-5f

// -------------------- scratch (static __device__, no allocation) -----------
__device__ float g_qkv  [Bb*Mm*D3];
__device__ float g_ao   [Bb*Mm*Dd];
__device__ float g_attn [Bb*Mm*Dd];
__device__ float g_S    [Bb*Ee*Dd];
__device__ float g_E0   [Bb*Ee*Dd];
__device__ float g_wef  [Bb*Mm*Dd];
__device__ float g_csum [Bb*Dd];
__device__ float g_wIn  [D3*Dd];
__device__ float g_wOut [Dd*Dd];
__device__ float g_wPv  [Dd*Dd];
__device__ float g_wPe  [Dd*Dd];

// -------------------- tf32 / async helpers ----------------------------------
__device__ __forceinline__ unsigned f2tf32(float x) {
    unsigned r;
    asm("cvt.rna.tf32.f32 %0, %1;" : "=r"(r) : "f"(x));
    return r;
}
__device__ __forceinline__ float round_tf32(float x) {
    return __uint_as_float(f2tf32(x));
}

__device__ __forceinline__ void mma_tf32(float c[4], const unsigned a[4], const unsigned b[2]) {
    asm volatile(
        "mma.sync.aligned.m16n8k8.row.col.f32.tf32.tf32.f32 "
        "{%0,%1,%2,%3}, {%4,%5,%6,%7}, {%8,%9}, {%0,%1,%2,%3};"
        : "+f"(c[0]), "+f"(c[1]), "+f"(c[2]), "+f"(c[3])
        : "r"(a[0]), "r"(a[1]), "r"(a[2]), "r"(a[3]), "r"(b[0]), "r"(b[1]));
}

__device__ __forceinline__ void cp_async16(void* smem_dst, const float* gsrc) {
    unsigned s = (unsigned)__cvta_generic_to_shared(smem_dst);
    asm volatile("cp.async.ca.shared.global [%0], [%1], 16;" :: "r"(s), "l"(gsrc));
}
#define CP_COMMIT() asm volatile("cp.async.commit_group;")

// -------------------- weight pre-round kernel (+ csum zero tail) ------------
__global__ void round_all_kernel(const float* __restrict__ w1, const float* __restrict__ w2,
                                 const float* __restrict__ w3, const float* __restrict__ w4,
                                 float* __restrict__ o1, float* __restrict__ o2,
                                 float* __restrict__ o3, float* __restrict__ o4,
                                 float* __restrict__ csum) {
    const size_t N1 = (size_t)D3 * Dd, N2 = (size_t)Dd * Dd;
    size_t i = (size_t)blockIdx.x * 256 + threadIdx.x;
    if (i < N1) { o1[i] = round_tf32(w1[i]); return; }
    i -= N1;
    if (i < N2) { o2[i] = round_tf32(w2[i]); return; }
    i -= N2;
    if (i < N2) { o3[i] = round_tf32(w3[i]); return; }
    i -= N2;
    if (i < N2) { o4[i] = round_tf32(w4[i]); return; }
    i -= N2;
    if (i < (size_t)Bb * Dd) csum[i] = 0.f;
}

// ============================================================================
// tf32 GEMM, cp.async NST-stage ring (guarded empty-commit tail so
// wait_group NST-2 is always exact). Tiling: 128x64x16, 4 warps, 64x32
// warp tiles, 3 CTAs/SM target.
//   TA==0: A stored [M,K]   TA==1: A stored [K,M]
//   TB==0: B stored [N,K]   TB==1: B stored [K,N]
//   CVTA: tf32-round A fragments at read (A may be raw fp32).
//   SUMEXP: epilogue column-sums exp(acc) into csum[z*Dd + col] (atomic).
// ============================================================================
template<int NST, int TA, int TB, bool HASBIAS, bool ROUND, bool SUMEXP, bool CVTA>
__global__ void __launch_bounds__(128, 3) gemm_tf32_kernel(
    const float* __restrict__ A, const float* __restrict__ B,
    const float* __restrict__ bias, float* __restrict__ C,
    int M, int N, int K, int lda, int ldb,
    long sA, long sB, long sC, float* __restrict__ csum)
{
    constexpr int ASZ = (TA == 0) ? 128 * 20 : 16 * 136;
    constexpr int BSZ = (TB == 0) ? 64 * 20 : 16 * 72;
    __shared__ float Asm[NST][ASZ];
    __shared__ float Bsm[NST][BSZ];

    int z = blockIdx.z;
    A += (size_t)z * sA; B += (size_t)z * sB; C += (size_t)z * sC;
    int i0 = blockIdx.y * 128, j0 = blockIdx.x * 64;
    int tid  = threadIdx.x;
    int warp = tid >> 5, lane = tid & 31, gid = lane >> 2, tig = lane & 3;
    int wr = warp >> 1, wc = warp & 1;

    int nkt = K >> 4;

    auto load_stage = [&](int st, int k0) {
        if (k0 < K) {
#pragma unroll
            for (int i = 0; i < 4; i++) {
                int c = tid + i * 128;
                if (TA == 0) { int m = c >> 2, j = (c & 3) << 2;
                    cp_async16(&Asm[st][m * 20 + j], A + (size_t)(i0 + m) * lda + k0 + j); }
                else         { int k = c >> 5, m = (c & 31) << 2;
                    cp_async16(&Asm[st][k * 136 + m], A + (size_t)(k0 + k) * lda + i0 + m); }
            }
#pragma unroll
            for (int i = 0; i < 2; i++) {
                int c = tid + i * 128;
                if (TB == 0) { int n = c >> 2, j = (c & 3) << 2;
                    cp_async16(&Bsm[st][n * 20 + j], B + (size_t)(j0 + n) * ldb + k0 + j); }
                else         { int k = c >> 4, n = (c & 15) << 2;
                    cp_async16(&Bsm[st][k * 72 + n], B + (size_t)(k0 + k) * ldb + j0 + n); }
            }
        }
        CP_COMMIT();
    };

    auto afrag = [&](unsigned raw) -> unsigned {
        return CVTA ? f2tf32(__uint_as_float(raw)) : raw;
    };

    float acc[4][4][4] = {};

#pragma unroll
    for (int s = 0; s < NST - 1; s++) load_stage(s, s << 4);

    for (int kt = 0; kt < nkt; kt++) {
        asm volatile("cp.async.wait_group %0;" :: "n"(NST - 2));
        __syncthreads();

        int cur = kt % NST;
        const unsigned* As = (const unsigned*)Asm[cur];
        const unsigned* Bs = (const unsigned*)Bsm[cur];
#pragma unroll
        for (int ks = 0; ks < 2; ks++) {
            int kk = ks * 8;
            unsigned a[4][4], bfr[4][2];
#pragma unroll
            for (int mt = 0; mt < 4; mt++) {
                int rb = wr * 64 + mt * 16;
                if (TA == 0) {
                    a[mt][0] = afrag(As[(rb + gid)     * 20 + kk + tig]);
                    a[mt][1] = afrag(As[(rb + gid + 8) * 20 + kk + tig]);
                    a[mt][2] = afrag(As[(rb + gid)     * 20 + kk + tig + 4]);
                    a[mt][3] = afrag(As[(rb + gid + 8) * 20 + kk + tig + 4]);
                } else {
                    a[mt][0] = As[(kk + tig)     * 136 + rb + gid];
                    a[mt][1] = As[(kk + tig)     * 136 + rb + gid + 8];
                    a[mt][2] = As[(kk + tig + 4) * 136 + rb + gid];
                    a[mt][3] = As[(kk + tig + 4) * 136 + rb + gid + 8];
                }
            }
#pragma unroll
            for (int nt = 0; nt < 4; nt++) {
                int nb = wc * 32 + nt * 8;
                if (TB == 0) {
                    bfr[nt][0] = Bs[(nb + gid) * 20 + kk + tig];
                    bfr[nt][1] = Bs[(nb + gid) * 20 + kk + tig + 4];
                } else {
                    bfr[nt][0] = Bs[(kk + tig)     * 72 + nb + gid];
                    bfr[nt][1] = Bs[(kk + tig + 4) * 72 + nb + gid];
                }
            }
#pragma unroll
            for (int mt = 0; mt < 4; mt++)
#pragma unroll
                for (int nt = 0; nt < 4; nt++)
                    mma_tf32(acc[mt][nt], a[mt], bfr[nt]);
        }
        load_stage((kt + NST - 1) % NST, (kt + NST - 1) << 4);
    }

#pragma unroll
    for (int mt = 0; mt < 4; mt++) {
        int row0 = i0 + wr * 64 + mt * 16 + gid;
#pragma unroll
        for (int nt = 0; nt < 4; nt++) {
            int col0 = j0 + wc * 32 + nt * 8 + 2 * tig;
            float b0 = HASBIAS ? bias[col0]     : 0.f;
            float b1 = HASBIAS ? bias[col0 + 1] : 0.f;
            float v00 = acc[mt][nt][0] + b0, v01 = acc[mt][nt][1] + b1;
            float v10 = acc[mt][nt][2] + b0, v11 = acc[mt][nt][3] + b1;
            if (ROUND) { v00 = round_tf32(v00); v01 = round_tf32(v01);
                         v10 = round_tf32(v10); v11 = round_tf32(v11); }
            C[(size_t)row0 * N + col0]           = v00;
            C[(size_t)row0 * N + col0 + 1]       = v01;
            C[(size_t)(row0 + 8) * N + col0]     = v10;
            C[(size_t)(row0 + 8) * N + col0 + 1] = v11;
        }
    }

    if (SUMEXP) {
#pragma unroll
        for (int nt = 0; nt < 4; nt++) {
            float e0 = 0.f, e1 = 0.f;
#pragma unroll
            for (int mt = 0; mt < 4; mt++) {
                e0 += __expf(acc[mt][nt][0]) + __expf(acc[mt][nt][2]);
                e1 += __expf(acc[mt][nt][1]) + __expf(acc[mt][nt][3]);
            }
#pragma unroll
            for (int o = 4; o <= 16; o <<= 1) {
                e0 += __shfl_xor_sync(0xffffffffu, e0, o);
                e1 += __shfl_xor_sync(0xffffffffu, e1, o);
            }
            if (gid == 0) {
                int col0 = j0 + wc * 32 + nt * 8 + 2 * tig;
                atomicAdd(&csum[z * Dd + col0],     e0);
                atomicAdd(&csum[z * Dd + col0 + 1], e1);
            }
        }
    }
}

// ============================================================================
// Fused GEMM (C tile ROWS x 256, full output row) + row-LayerNorm epilogue.
//   EPI==0: A-load applies edge-weight transform round(s*exp(s)/csum);
//           E0 = round(LN(C)); out2 = (3+va)*LN(C)       [edge path]
//   EPI==1: A pre-rounded (cp.async); 3-step recurrence -> out1 [node path]
// 2 CTAs/SM.
// ============================================================================
template<int MT, int EPI>
__global__ void __launch_bounds__(256, 2) gemm_ln_kernel(
    const float* __restrict__ A, const float* __restrict__ W,
    const float* __restrict__ g, const float* __restrict__ bt,
    const float* __restrict__ a1,   // EPI0: va   EPI1: ea
    const float* __restrict__ a2,   // EPI1: va
    const float* __restrict__ aux,  // EPI0: csum[Bb*Dd]   EPI1: feat
    float* __restrict__ out1, float* __restrict__ out2)
{
    constexpr int ROWS = MT * 32;
    __shared__ float Asm[2][ROWS * 20];
    __shared__ float Bsm[2][256 * 20];
    __shared__ float invc[EPI == 0 ? 256 : 1];

    int i0 = blockIdx.y * ROWS;
    int tid = threadIdx.x;
    int warp = tid >> 5, lane = tid & 31, gid = lane >> 2, tig = lane & 3;
    int wr = warp >> 2, wc = warp & 3;

    if (EPI == 0) {
        int bidx = i0 / Ee;
        invc[tid] = 1.0f / aux[bidx * Dd + tid];
    }

    auto load_B = [&](int st, int k0) {
#pragma unroll
        for (int i = 0; i < 4; i++) {
            int c = tid + i * 256;
            int n = c >> 2, j = (c & 3) << 2;
            cp_async16(&Bsm[st][n * 20 + j], W + (size_t)n * 256 + k0 + j);
        }
        CP_COMMIT();
    };
    auto load_A_async = [&](int st, int k0) {
#pragma unroll
        for (int i = 0; i < ROWS / 64; i++) {
            int c = tid + i * 256;
            int m = c >> 2, j = (c & 3) << 2;
            cp_async16(&Asm[st][m * 20 + j], A + (size_t)(i0 + m) * 256 + k0 + j);
        }
    };

    float4 ar[ROWS / 64][1];
    int a_m[ROWS / 64], a_j[ROWS / 64];
#pragma unroll
    for (int i = 0; i < ROWS / 64; i++) {
        int c = tid + i * 256;
        a_m[i] = c >> 2; a_j[i] = (c & 3) << 2;
    }
    auto ldg_A = [&](int k0) {
#pragma unroll
        for (int i = 0; i < ROWS / 64; i++)
            ar[i][0] = *(const float4*)(A + (size_t)(i0 + a_m[i]) * 256 + k0 + a_j[i]);
    };
    auto sts_A_transformed = [&](int st, int k0) {
#pragma unroll
        for (int i = 0; i < ROWS / 64; i++) {
            float v[4] = {ar[i][0].x, ar[i][0].y, ar[i][0].z, ar[i][0].w};
            float o[4];
#pragma unroll
            for (int l = 0; l < 4; l++)
                o[l] = round_tf32(v[l] * __expf(v[l]) * invc[k0 + a_j[i] + l]);
            float* d = &Asm[st][a_m[i] * 20 + a_j[i]];
            d[0] = o[0]; d[1] = o[1]; d[2] = o[2]; d[3] = o[3];
        }
    };

    float acc[MT][8][4] = {};

    if (EPI == 0) { ldg_A(0); load_B(0, 0); __syncthreads(); }
    else          { load_A_async(0, 0); load_B(0, 0); }

    for (int kt = 0; kt < 16; kt++) {
        int st = kt & 1;
        if (EPI == 0) {
            asm volatile("cp.async.wait_group 0;");
            sts_A_transformed(st, kt << 4);
            __syncthreads();
            if (kt + 1 < 16) { ldg_A((kt + 1) << 4); load_B(st ^ 1, (kt + 1) << 4); }
        } else {
            asm volatile("cp.async.wait_group 0;");
            __syncthreads();
            if (kt + 1 < 16) { load_A_async(st ^ 1, (kt + 1) << 4); load_B(st ^ 1, (kt + 1) << 4); }
        }
        const unsigned* As = (const unsigned*)Asm[st];
        const unsigned* Bs = (const unsigned*)Bsm[st];
#pragma unroll
        for (int ks = 0; ks < 2; ks++) {
            int kk = ks * 8;
            unsigned a[MT][4], bfr[8][2];
#pragma unroll
            for (int mt = 0; mt < MT; mt++) {
                int rb = wr * (MT * 16) + mt * 16;
                a[mt][0] = As[(rb + gid)     * 20 + kk + tig];
                a[mt][1] = As[(rb + gid + 8) * 20 + kk + tig];
                a[mt][2] = As[(rb + gid)     * 20 + kk + tig + 4];
                a[mt][3] = As[(rb + gid + 8) * 20 + kk + tig + 4];
            }
#pragma unroll
            for (int nt = 0; nt < 8; nt++) {
                int nb = wc * 64 + nt * 8;
                bfr[nt][0] = Bs[(nb + gid) * 20 + kk + tig];
                bfr[nt][1] = Bs[(nb + gid) * 20 + kk + tig + 4];
            }
#pragma unroll
            for (int mt = 0; mt < MT; mt++)
#pragma unroll
                for (int nt = 0; nt < 8; nt++)
                    mma_tf32(acc[mt][nt], a[mt], bfr[nt]);
        }
        if (kt + 1 < 16) __syncthreads();
    }

    __syncthreads();
    float* red  = (float*)Asm;
    float* red2 = red + ROWS * 4;
#pragma unroll
    for (int mt = 0; mt < MT; mt++) {
        float s0 = 0.f, q0 = 0.f, s1 = 0.f, q1 = 0.f;
#pragma unroll
        for (int nt = 0; nt < 8; nt++) {
            const float* c = acc[mt][nt];
            s0 += c[0] + c[1]; q0 += c[0] * c[0] + c[1] * c[1];
            s1 += c[2] + c[3]; q1 += c[2] * c[2] + c[3] * c[3];
        }
#pragma unroll
        for (int o = 1; o <= 2; o <<= 1) {
            s0 += __shfl_xor_sync(0xffffffffu, s0, o);
            q0 += __shfl_xor_sync(0xffffffffu, q0, o);
            s1 += __shfl_xor_sync(0xffffffffu, s1, o);
            q1 += __shfl_xor_sync(0xffffffffu, q1, o);
        }
        if (tig == 0) {
            int r = wr * (MT * 16) + mt * 16 + gid;
            red [r * 4 + wc] = s0;  red2[r * 4 + wc] = q0;
            red [(r + 8) * 4 + wc] = s1;  red2[(r + 8) * 4 + wc] = q1;
        }
    }
    __syncthreads();

    float ea = 0.f, va = 0.f;
    if (EPI == 0) va = *a1;
    else { ea = *a1; va = *a2; }
    float c2 = 3.0f + va;

#pragma unroll
    for (int mt = 0; mt < MT; mt++) {
        int rl0 = wr * (MT * 16) + mt * 16 + gid;
        float mu[2], var[2];
#pragma unroll
        for (int h = 0; h < 2; h++) {
            int rl = rl0 + 8 * h;
            float S  = red [rl * 4] + red [rl * 4 + 1] + red [rl * 4 + 2] + red [rl * 4 + 3];
            float S2 = red2[rl * 4] + red2[rl * 4 + 1] + red2[rl * 4 + 2] + red2[rl * 4 + 3];
            mu[h]  = S * (1.0f / Dd);
            var[h] = S2 * (1.0f / Dd) - mu[h] * mu[h];
        }
        float rsA[2], rsB[2], rsC[2];
#pragma unroll
        for (int h = 0; h < 2; h++) {
            rsA[h] = rsqrtf(var[h] + LNEPS);
            if (EPI == 1) {
                rsB[h] = 2.0f * rsqrtf(4.0f * var[h] + LNEPS);
                rsC[h] = c2 * rsqrtf(c2 * c2 * var[h] + LNEPS);
            }
        }
#pragma unroll
        for (int nt = 0; nt < 8; nt++) {
            int col0 = wc * 64 + nt * 8 + 2 * tig;
            float gg0 = g[col0], gg1 = g[col0 + 1];
            float bb0 = bt[col0], bb1 = bt[col0 + 1];
#pragma unroll
            for (int h = 0; h < 2; h++) {
                size_t ro = (size_t)(i0 + rl0 + 8 * h) * Dd + col0;
                float dx0 = acc[mt][nt][2 * h]     - mu[h];
                float dx1 = acc[mt][nt][2 * h + 1] - mu[h];
                if (EPI == 0) {
                    float y0 = dx0 * rsA[h] * gg0 + bb0;
                    float y1 = dx1 * rsA[h] * gg1 + bb1;
                    out1[ro]     = round_tf32(y0);
                    out1[ro + 1] = round_tf32(y1);
                    out2[ro]     = c2 * y0;
                    out2[ro + 1] = c2 * y1;
                } else {
                    float f0 = aux[ro], f1 = aux[ro + 1];
                    float ya0 = dx0 * rsA[h] * gg0 + bb0, ya1 = dx1 * rsA[h] * gg1 + bb1;
                    float yb0 = dx0 * rsB[h] * gg0 + bb0, yb1 = dx1 * rsB[h] * gg1 + bb1;
                    float yc0 = dx0 * rsC[h] * gg0 + bb0, yc1 = dx1 * rsC[h] * gg1 + bb1;
                    float n0 = (1.0f + ea) * f0 + (1.0f - ea) * ya0;
                    n0 = (1.0f + ea) * n0 + (1.0f - ea) * yb0;
                    n0 = (1.0f + ea) * n0 + (1.0f - ea) * yc0;
                    float n1 = (1.0f + ea) * f1 + (1.0f - ea) * ya1;
                    n1 = (1.0f + ea) * n1 + (1.0f - ea) * yb1;
                    n1 = (1.0f + ea) * n1 + (1.0f - ea) * yc1;
                    out1[ro]     = n0;
                    out1[ro + 1] = n1;
                }
            }
        }
    }
}

// ============================================================================
// tf32 flash attention (R11 shape) + embedded inc->out_inc copy.
// ============================================================================
__global__ void __launch_bounds__(256, 2) attn_tf32_kernel(
    const float* __restrict__ qkv, float* __restrict__ ao,
    const float* __restrict__ inc, float* __restrict__ out_inc)
{
    __shared__ unsigned Qs[64][36];
    __shared__ unsigned Ks[2][64][36];
    __shared__ unsigned Vs[2][64][36];   // [key][d]
    __shared__ unsigned Ps[64][68];      // exp(S) as tf32 bits
    __shared__ float    lrow[64];

    int bh = blockIdx.y; int b = bh >> 3; int h = bh & 7;
    int q0 = blockIdx.x * 64;
    int tid = threadIdx.x;
    int warp = tid >> 5, lane = tid & 31, gid = lane >> 2, tig = lane & 3;
    int wm = warp >> 2, wn = warp & 3;       // S-mma 2x4
    int wm2 = warp >> 1, wn2 = warp & 1;     // PV-mma 4x2
    const float scale = 0.17677669529663687f;

    size_t cbase = ((size_t)bh * gridDim.x + blockIdx.x) * 12288 + (size_t)tid * 4;

    auto load_kv = [&](int st, int kbase) {
#pragma unroll
        for (int i = 0; i < 2; i++) {
            int c = tid + i * 256;
            int m = c >> 3, j = (c & 7) << 2;
            const float* row = qkv + (size_t)(b * Mm + kbase + m) * D3 + h * DHd + j;
            cp_async16(&Ks[st][m][j], row + Dd);
            cp_async16(&Vs[st][m][j], row + 2 * Dd);
        }
        CP_COMMIT();
    };

#pragma unroll
    for (int i = 0; i < 2; i++) {
        int c = tid + i * 256;
        int m = c >> 3, j = (c & 7) << 2;
        cp_async16(&Qs[m][j], qkv + (size_t)(b * Mm + q0 + m) * D3 + h * DHd + j);
    }
    load_kv(0, 0);
    if (tid < 64) lrow[tid] = 0.f;

    float o[2][4] = {};
    int srow = tid >> 2, squad = tid & 3;

    for (int kt = 0; kt < Mm / 64; kt++) {
        int cur = kt & 1;
        asm volatile("cp.async.wait_group 0;");
        __syncthreads();
        if (kt + 1 < Mm / 64) load_kv(cur ^ 1, (kt + 1) * 64);

        float4 cpv;
        bool do_cp = (kt < 12);
        size_t coff = cbase + (size_t)kt * 1024;
        if (do_cp) cpv = *(const float4*)(inc + coff);

        float s[2][2][4] = {};
#pragma unroll
        for (int ks = 0; ks < 4; ks++) {
            int kk = ks * 8;
            unsigned a[2][4], bfr[2][2];
#pragma unroll
            for (int mt = 0; mt < 2; mt++) {
                int rb = wm * 32 + mt * 16;
                a[mt][0] = Qs[rb + gid    ][kk + tig];
                a[mt][1] = Qs[rb + gid + 8][kk + tig];
                a[mt][2] = Qs[rb + gid    ][kk + tig + 4];
                a[mt][3] = Qs[rb + gid + 8][kk + tig + 4];
            }
#pragma unroll
            for (int nt = 0; nt < 2; nt++) {
                int nb = wn * 16 + nt * 8;
                bfr[nt][0] = Ks[cur][nb + gid][kk + tig];
                bfr[nt][1] = Ks[cur][nb + gid][kk + tig + 4];
            }
#pragma unroll
            for (int mt = 0; mt < 2; mt++)
#pragma unroll
                for (int nt = 0; nt < 2; nt++)
                    mma_tf32(s[mt][nt], a[mt], bfr[nt]);
        }

#pragma unroll
        for (int mt = 0; mt < 2; mt++) {
            int r0 = wm * 32 + mt * 16 + gid;
#pragma unroll
            for (int nt = 0; nt < 2; nt++) {
                int c0 = wn * 16 + nt * 8 + 2 * tig;
                Ps[r0    ][c0    ] = f2tf32(__expf(s[mt][nt][0] * scale));
                Ps[r0    ][c0 + 1] = f2tf32(__expf(s[mt][nt][1] * scale));
                Ps[r0 + 8][c0    ] = f2tf32(__expf(s[mt][nt][2] * scale));
                Ps[r0 + 8][c0 + 1] = f2tf32(__expf(s[mt][nt][3] * scale));
            }
        }
        __syncthreads();

        {
            float sm = 0.f;
#pragma unroll
            for (int j = 0; j < 16; j++)
                sm += __uint_as_float(Ps[srow][squad * 16 + j]);
            sm += __shfl_xor_sync(0xffffffffu, sm, 1);
            sm += __shfl_xor_sync(0xffffffffu, sm, 2);
            if (squad == 0) lrow[srow] += sm;
        }

        {
            int rb2 = wm2 * 16;
#pragma unroll
            for (int ks = 0; ks < 8; ks++) {
                int kk = ks * 8;
                unsigned a[4], bfr[2][2];
                a[0] = Ps[rb2 + gid    ][kk + tig];
                a[1] = Ps[rb2 + gid + 8][kk + tig];
                a[2] = Ps[rb2 + gid    ][kk + tig + 4];
                a[3] = Ps[rb2 + gid + 8][kk + tig + 4];
#pragma unroll
                for (int nt = 0; nt < 2; nt++) {
                    int nb = wn2 * 16 + nt * 8;
                    bfr[nt][0] = Vs[cur][kk + tig    ][nb + gid];
                    bfr[nt][1] = Vs[cur][kk + tig + 4][nb + gid];
                }
#pragma unroll
                for (int nt = 0; nt < 2; nt++)
                    mma_tf32(o[nt], a, bfr[nt]);
            }
        }

        if (do_cp) *(float4*)(out_inc + coff) = cpv;
    }
    __syncthreads();

    int r0 = wm2 * 16 + gid;
    float inv0 = 1.0f / lrow[r0];
    float inv8 = 1.0f / lrow[r0 + 8];
#pragma unroll
    for (int nt = 0; nt < 2; nt++) {
        int c0 = wn2 * 16 + nt * 8 + 2 * tig;
        size_t base0 = (size_t)(b * Mm + q0 + r0) * Dd + h * DHd + c0;
        size_t base8 = (size_t)(b * Mm + q0 + r0 + 8) * Dd + h * DHd + c0;
        ao[base0]     = round_tf32(o[nt][0] * inv0);
        ao[base0 + 1] = round_tf32(o[nt][1] * inv0);
        ao[base8]     = round_tf32(o[nt][2] * inv8);
        ao[base8 + 1] = round_tf32(o[nt][3] * inv8);
    }
}

// ============================================================================
extern "C" void kernel_launch(void* const* d_in, const int* in_sizes, int n_in,
                              void* d_out, int out_size) {
    const float* features = (const float*)d_in[0];
    const float* inc      = (const float*)d_in[1];
    const float* vc_Win   = (const float*)d_in[2];
    const float* vc_bin   = (const float*)d_in[3];
    const float* vc_Wout  = (const float*)d_in[4];
    const float* vc_bout  = (const float*)d_in[5];
    const float* vc_Wproj = (const float*)d_in[6];
    const float* vc_ln_g  = (const float*)d_in[7];
    const float* vc_ln_b  = (const float*)d_in[8];
    const float* vc_alpha = (const float*)d_in[9];
    const float* ec_Wproj = (const float*)d_in[14];
    const float* ec_ln_g  = (const float*)d_in[15];
    const float* ec_ln_b  = (const float*)d_in[16];
    const float* ec_alpha = (const float*)d_in[17];

    float* out      = (float*)d_out;
    float* out_node = out;
    float* out_edge = out + (size_t)Bb * Mm * Dd;
    float* out_inc  = out_edge + (size_t)Bb * Ee * Dd;

    float *qkv, *ao, *attn, *S, *E0, *wef, *csum;
    float *wIn, *wOut, *wPv, *wPe;
    cudaGetSymbolAddress((void**)&qkv,   g_qkv);
    cudaGetSymbolAddress((void**)&ao,    g_ao);
    cudaGetSymbolAddress((void**)&attn,  g_attn);
    cudaGetSymbolAddress((void**)&S,     g_S);
    cudaGetSymbolAddress((void**)&E0,    g_E0);
    cudaGetSymbolAddress((void**)&wef,   g_wef);
    cudaGetSymbolAddress((void**)&csum,  g_csum);
    cudaGetSymbolAddress((void**)&wIn,   g_wIn);
    cudaGetSymbolAddress((void**)&wOut,  g_wOut);
    cudaGetSymbolAddress((void**)&wPv,   g_wPv);
    cudaGetSymbolAddress((void**)&wPe,   g_wPe);

    // 0) pre-round weight operands + zero csum (one small kernel)
    {
        size_t tot = (size_t)D3 * Dd + 3 * (size_t)Dd * Dd + (size_t)Bb * Dd;
        round_all_kernel<<<(int)((tot + 255) / 256), 256>>>(
            vc_Win, vc_Wout, vc_Wproj, ec_Wproj,
            wIn, wOut, wPv, wPe, csum);
    }

    // 1) QKV = features @ vc_Win^T + vc_bin  (A rounded at fragment read)
    gemm_tf32_kernel<3, 0, 0, true, true, false, true><<<dim3(D3 / 64, (Bb * Mm) / 128, 1), 128>>>(
        features, wIn, vc_bin, qkv, Bb * Mm, D3, Dd, Dd, Dd, 0, 0, 0, nullptr);

    // 2) flash attention -> ao (rounded) + embedded inc passthrough copy
    attn_tf32_kernel<<<dim3(Mm / 64, Bb * Hh), 256>>>(qkv, ao, inc, out_inc);

    // 3) attn = ao @ vc_Wout^T + vc_bout (rounded)
    gemm_tf32_kernel<3, 0, 0, true, true, false, false><<<dim3(Dd / 64, (Bb * Mm) / 128, 1), 128>>>(
        ao, wOut, vc_bout, attn, Bb * Mm, Dd, Dd, Dd, Dd, 0, 0, 0, nullptr);

    // 4) S = inc^T @ attn + fused exp column sums — 5-stage ring (K=1024)
    gemm_tf32_kernel<5, 1, 1, false, false, true, false><<<dim3(Dd / 64, Ee / 128, Bb), 128>>>(
        inc, attn, nullptr, S, Ee, Dd, Mm, Ee, Dd,
        (long)Mm * Ee, (long)Mm * Dd, (long)Ee * Dd, csum);

    // 6+7) fused: edge-weight transform + (edge @ vc_Wproj^T) -> LN -> E0 + out_edge
    gemm_ln_kernel<2, 0><<<dim3(1, (Bb * Ee) / 64), 256>>>(
        S, wPv, vc_ln_g, vc_ln_b, vc_alpha, nullptr, csum, E0, out_edge);

    // 8) wef = inc @ E0 (rounded) — 4-stage ring (K=1536)
    gemm_tf32_kernel<4, 0, 1, false, true, false, false><<<dim3(Dd / 64, Mm / 128, Bb), 128>>>(
        inc, E0, nullptr, wef, Mm, Dd, Ee, Ee, Dd,
        (long)Mm * Ee, (long)Ee * Dd, (long)Mm * Dd, nullptr);

    // 9) fused: (wef @ ec_Wproj^T) -> LN -> 3-step recurrence -> out_node
    gemm_ln_kernel<2, 1><<<dim3(1, (Bb * Mm) / 64), 256>>>(
        wef, wPe, ec_ln_g, ec_ln_b, ec_alpha, vc_alpha, features, out_node, nullptr);
}

// round 16
// speedup vs baseline: 1.0392x; 1.0024x over previous
#include <cuda_runtime.h>
#include <math.h>

#define Bb 8
#define Mm 1024
#define Ee 1536
#define Dd 256
#define Hh 8
#define DHd 32
#define D3 768
#define LNEPS 1e-5f

// -------------------- scratch (static __device__, no allocation) -----------
__device__ float g_qkv  [Bb*Mm*D3];
__device__ float g_ao   [Bb*Mm*Dd];
__device__ float g_attn [Bb*Mm*Dd];
__device__ float g_S    [Bb*Ee*Dd];
__device__ float g_E0   [Bb*Ee*Dd];
__device__ float g_wef  [Bb*Mm*Dd];
__device__ float g_csum [Bb*Dd];

// -------------------- tf32 / async helpers ----------------------------------
__device__ __forceinline__ unsigned f2tf32(float x) {
    unsigned r;
    asm("cvt.rna.tf32.f32 %0, %1;" : "=r"(r) : "f"(x));
    return r;
}
__device__ __forceinline__ float round_tf32(float x) {
    return __uint_as_float(f2tf32(x));
}

__device__ __forceinline__ void mma_tf32(float c[4], const unsigned a[4], const unsigned b[2]) {
    asm volatile(
        "mma.sync.aligned.m16n8k8.row.col.f32.tf32.tf32.f32 "
        "{%0,%1,%2,%3}, {%4,%5,%6,%7}, {%8,%9}, {%0,%1,%2,%3};"
        : "+f"(c[0]), "+f"(c[1]), "+f"(c[2]), "+f"(c[3])
        : "r"(a[0]), "r"(a[1]), "r"(a[2]), "r"(a[3]), "r"(b[0]), "r"(b[1]));
}

__device__ __forceinline__ void cp_async16(void* smem_dst, const float* gsrc) {
    unsigned s = (unsigned)__cvta_generic_to_shared(smem_dst);
    asm volatile("cp.async.ca.shared.global [%0], [%1], 16;" :: "r"(s), "l"(gsrc));
}
#define CP_COMMIT() asm volatile("cp.async.commit_group;")

// ============================================================================
// tf32 GEMM, cp.async NST-stage ring (guarded empty-commit tail).
// Tiling: 128x64x16, 4 warps, 64x32 warp tiles, 3 CTAs/SM target.
//   TA==0: A stored [M,K]   TA==1: A stored [K,M]
//   TB==0: B stored [N,K]   TB==1: B stored [K,N]
//   CVTA/CVTB: tf32-round A/B fragments at read (operand may be raw fp32).
//   SUMEXP: epilogue column-sums exp(acc) into csum[z*Dd + col] (atomic).
// ============================================================================
template<int NST, int TA, int TB, bool HASBIAS, bool ROUND, bool SUMEXP,
         bool CVTA, bool CVTB>
__global__ void __launch_bounds__(128, 3) gemm_tf32_kernel(
    const float* __restrict__ A, const float* __restrict__ B,
    const float* __restrict__ bias, float* __restrict__ C,
    int M, int N, int K, int lda, int ldb,
    long sA, long sB, long sC, float* __restrict__ csum)
{
    constexpr int ASZ = (TA == 0) ? 128 * 20 : 16 * 136;
    constexpr int BSZ = (TB == 0) ? 64 * 20 : 16 * 72;
    __shared__ float Asm[NST][ASZ];
    __shared__ float Bsm[NST][BSZ];

    int z = blockIdx.z;
    A += (size_t)z * sA; B += (size_t)z * sB; C += (size_t)z * sC;
    int i0 = blockIdx.y * 128, j0 = blockIdx.x * 64;
    int tid  = threadIdx.x;
    int warp = tid >> 5, lane = tid & 31, gid = lane >> 2, tig = lane & 3;
    int wr = warp >> 1, wc = warp & 1;

    int nkt = K >> 4;

    auto load_stage = [&](int st, int k0) {
        if (k0 < K) {
#pragma unroll
            for (int i = 0; i < 4; i++) {
                int c = tid + i * 128;
                if (TA == 0) { int m = c >> 2, j = (c & 3) << 2;
                    cp_async16(&Asm[st][m * 20 + j], A + (size_t)(i0 + m) * lda + k0 + j); }
                else         { int k = c >> 5, m = (c & 31) << 2;
                    cp_async16(&Asm[st][k * 136 + m], A + (size_t)(k0 + k) * lda + i0 + m); }
            }
#pragma unroll
            for (int i = 0; i < 2; i++) {
                int c = tid + i * 128;
                if (TB == 0) { int n = c >> 2, j = (c & 3) << 2;
                    cp_async16(&Bsm[st][n * 20 + j], B + (size_t)(j0 + n) * ldb + k0 + j); }
                else         { int k = c >> 4, n = (c & 15) << 2;
                    cp_async16(&Bsm[st][k * 72 + n], B + (size_t)(k0 + k) * ldb + j0 + n); }
            }
        }
        CP_COMMIT();
    };

    auto afrag = [&](unsigned raw) -> unsigned {
        return CVTA ? f2tf32(__uint_as_float(raw)) : raw;
    };
    auto bfrag = [&](unsigned raw) -> unsigned {
        return CVTB ? f2tf32(__uint_as_float(raw)) : raw;
    };

    float acc[4][4][4] = {};

#pragma unroll
    for (int s = 0; s < NST - 1; s++) load_stage(s, s << 4);

    for (int kt = 0; kt < nkt; kt++) {
        asm volatile("cp.async.wait_group %0;" :: "n"(NST - 2));
        __syncthreads();

        int cur = kt % NST;
        const unsigned* As = (const unsigned*)Asm[cur];
        const unsigned* Bs = (const unsigned*)Bsm[cur];
#pragma unroll
        for (int ks = 0; ks < 2; ks++) {
            int kk = ks * 8;
            unsigned a[4][4], bfr[4][2];
#pragma unroll
            for (int mt = 0; mt < 4; mt++) {
                int rb = wr * 64 + mt * 16;
                if (TA == 0) {
                    a[mt][0] = afrag(As[(rb + gid)     * 20 + kk + tig]);
                    a[mt][1] = afrag(As[(rb + gid + 8) * 20 + kk + tig]);
                    a[mt][2] = afrag(As[(rb + gid)     * 20 + kk + tig + 4]);
                    a[mt][3] = afrag(As[(rb + gid + 8) * 20 + kk + tig + 4]);
                } else {
                    a[mt][0] = As[(kk + tig)     * 136 + rb + gid];
                    a[mt][1] = As[(kk + tig)     * 136 + rb + gid + 8];
                    a[mt][2] = As[(kk + tig + 4) * 136 + rb + gid];
                    a[mt][3] = As[(kk + tig + 4) * 136 + rb + gid + 8];
                }
            }
#pragma unroll
            for (int nt = 0; nt < 4; nt++) {
                int nb = wc * 32 + nt * 8;
                if (TB == 0) {
                    bfr[nt][0] = bfrag(Bs[(nb + gid) * 20 + kk + tig]);
                    bfr[nt][1] = bfrag(Bs[(nb + gid) * 20 + kk + tig + 4]);
                } else {
                    bfr[nt][0] = Bs[(kk + tig)     * 72 + nb + gid];
                    bfr[nt][1] = Bs[(kk + tig + 4) * 72 + nb + gid];
                }
            }
#pragma unroll
            for (int mt = 0; mt < 4; mt++)
#pragma unroll
                for (int nt = 0; nt < 4; nt++)
                    mma_tf32(acc[mt][nt], a[mt], bfr[nt]);
        }
        load_stage((kt + NST - 1) % NST, (kt + NST - 1) << 4);
    }

#pragma unroll
    for (int mt = 0; mt < 4; mt++) {
        int row0 = i0 + wr * 64 + mt * 16 + gid;
#pragma unroll
        for (int nt = 0; nt < 4; nt++) {
            int col0 = j0 + wc * 32 + nt * 8 + 2 * tig;
            float b0 = HASBIAS ? bias[col0]     : 0.f;
            float b1 = HASBIAS ? bias[col0 + 1] : 0.f;
            float v00 = acc[mt][nt][0] + b0, v01 = acc[mt][nt][1] + b1;
            float v10 = acc[mt][nt][2] + b0, v11 = acc[mt][nt][3] + b1;
            if (ROUND) { v00 = round_tf32(v00); v01 = round_tf32(v01);
                         v10 = round_tf32(v10); v11 = round_tf32(v11); }
            C[(size_t)row0 * N + col0]           = v00;
            C[(size_t)row0 * N + col0 + 1]       = v01;
            C[(size_t)(row0 + 8) * N + col0]     = v10;
            C[(size_t)(row0 + 8) * N + col0 + 1] = v11;
        }
    }

    if (SUMEXP) {
#pragma unroll
        for (int nt = 0; nt < 4; nt++) {
            float e0 = 0.f, e1 = 0.f;
#pragma unroll
            for (int mt = 0; mt < 4; mt++) {
                e0 += __expf(acc[mt][nt][0]) + __expf(acc[mt][nt][2]);
                e1 += __expf(acc[mt][nt][1]) + __expf(acc[mt][nt][3]);
            }
#pragma unroll
            for (int o = 4; o <= 16; o <<= 1) {
                e0 += __shfl_xor_sync(0xffffffffu, e0, o);
                e1 += __shfl_xor_sync(0xffffffffu, e1, o);
            }
            if (gid == 0) {
                int col0 = j0 + wc * 32 + nt * 8 + 2 * tig;
                atomicAdd(&csum[z * Dd + col0],     e0);
                atomicAdd(&csum[z * Dd + col0 + 1], e1);
            }
        }
    }
}

// ============================================================================
// Fused GEMM (C tile ROWS x 256) + row-LayerNorm epilogue. W raw fp32,
// tf32-rounded at fragment read (bit-identical to pre-rounding).
//   EPI==0: A-load applies edge-weight transform round(s*exp(s)/csum);
//           E0 = round(LN(C)); out2 = (3+va)*LN(C)       [edge path]
//   EPI==1: A pre-rounded (cp.async); 3-step recurrence -> out1 [node path]
// ============================================================================
template<int MT, int EPI>
__global__ void __launch_bounds__(256, 2) gemm_ln_kernel(
    const float* __restrict__ A, const float* __restrict__ W,
    const float* __restrict__ g, const float* __restrict__ bt,
    const float* __restrict__ a1,   // EPI0: va   EPI1: ea
    const float* __restrict__ a2,   // EPI1: va
    const float* __restrict__ aux,  // EPI0: csum[Bb*Dd]   EPI1: feat
    float* __restrict__ out1, float* __restrict__ out2)
{
    constexpr int ROWS = MT * 32;
    __shared__ float Asm[2][ROWS * 20];
    __shared__ float Bsm[2][256 * 20];
    __shared__ float invc[EPI == 0 ? 256 : 1];

    int i0 = blockIdx.y * ROWS;
    int tid = threadIdx.x;
    int warp = tid >> 5, lane = tid & 31, gid = lane >> 2, tig = lane & 3;
    int wr = warp >> 2, wc = warp & 3;

    if (EPI == 0) {
        int bidx = i0 / Ee;
        invc[tid] = 1.0f / aux[bidx * Dd + tid];
    }

    auto load_B = [&](int st, int k0) {
#pragma unroll
        for (int i = 0; i < 4; i++) {
            int c = tid + i * 256;
            int n = c >> 2, j = (c & 3) << 2;
            cp_async16(&Bsm[st][n * 20 + j], W + (size_t)n * 256 + k0 + j);
        }
        CP_COMMIT();
    };
    auto load_A_async = [&](int st, int k0) {
#pragma unroll
        for (int i = 0; i < ROWS / 64; i++) {
            int c = tid + i * 256;
            int m = c >> 2, j = (c & 3) << 2;
            cp_async16(&Asm[st][m * 20 + j], A + (size_t)(i0 + m) * 256 + k0 + j);
        }
    };

    float4 ar[ROWS / 64][1];
    int a_m[ROWS / 64], a_j[ROWS / 64];
#pragma unroll
    for (int i = 0; i < ROWS / 64; i++) {
        int c = tid + i * 256;
        a_m[i] = c >> 2; a_j[i] = (c & 3) << 2;
    }
    auto ldg_A = [&](int k0) {
#pragma unroll
        for (int i = 0; i < ROWS / 64; i++)
            ar[i][0] = *(const float4*)(A + (size_t)(i0 + a_m[i]) * 256 + k0 + a_j[i]);
    };
    auto sts_A_transformed = [&](int st, int k0) {
#pragma unroll
        for (int i = 0; i < ROWS / 64; i++) {
            float v[4] = {ar[i][0].x, ar[i][0].y, ar[i][0].z, ar[i][0].w};
            float o[4];
#pragma unroll
            for (int l = 0; l < 4; l++)
                o[l] = round_tf32(v[l] * __expf(v[l]) * invc[k0 + a_j[i] + l]);
            float* d = &Asm[st][a_m[i] * 20 + a_j[i]];
            d[0] = o[0]; d[1] = o[1]; d[2] = o[2]; d[3] = o[3];
        }
    };

    float acc[MT][8][4] = {};

    if (EPI == 0) { ldg_A(0); load_B(0, 0); __syncthreads(); }
    else          { load_A_async(0, 0); load_B(0, 0); }

    for (int kt = 0; kt < 16; kt++) {
        int st = kt & 1;
        if (EPI == 0) {
            asm volatile("cp.async.wait_group 0;");
            sts_A_transformed(st, kt << 4);
            __syncthreads();
            if (kt + 1 < 16) { ldg_A((kt + 1) << 4); load_B(st ^ 1, (kt + 1) << 4); }
        } else {
            asm volatile("cp.async.wait_group 0;");
            __syncthreads();
            if (kt + 1 < 16) { load_A_async(st ^ 1, (kt + 1) << 4); load_B(st ^ 1, (kt + 1) << 4); }
        }
        const unsigned* As = (const unsigned*)Asm[st];
        const unsigned* Bs = (const unsigned*)Bsm[st];
#pragma unroll
        for (int ks = 0; ks < 2; ks++) {
            int kk = ks * 8;
            unsigned a[MT][4], bfr[8][2];
#pragma unroll
            for (int mt = 0; mt < MT; mt++) {
                int rb = wr * (MT * 16) + mt * 16;
                a[mt][0] = As[(rb + gid)     * 20 + kk + tig];
                a[mt][1] = As[(rb + gid + 8) * 20 + kk + tig];
                a[mt][2] = As[(rb + gid)     * 20 + kk + tig + 4];
                a[mt][3] = As[(rb + gid + 8) * 20 + kk + tig + 4];
            }
#pragma unroll
            for (int nt = 0; nt < 8; nt++) {
                int nb = wc * 64 + nt * 8;
                bfr[nt][0] = f2tf32(__uint_as_float(Bs[(nb + gid) * 20 + kk + tig]));
                bfr[nt][1] = f2tf32(__uint_as_float(Bs[(nb + gid) * 20 + kk + tig + 4]));
            }
#pragma unroll
            for (int mt = 0; mt < MT; mt++)
#pragma unroll
                for (int nt = 0; nt < 8; nt++)
                    mma_tf32(acc[mt][nt], a[mt], bfr[nt]);
        }
        if (kt + 1 < 16) __syncthreads();
    }

    __syncthreads();
    float* red  = (float*)Asm;
    float* red2 = red + ROWS * 4;
#pragma unroll
    for (int mt = 0; mt < MT; mt++) {
        float s0 = 0.f, q0 = 0.f, s1 = 0.f, q1 = 0.f;
#pragma unroll
        for (int nt = 0; nt < 8; nt++) {
            const float* c = acc[mt][nt];
            s0 += c[0] + c[1]; q0 += c[0] * c[0] + c[1] * c[1];
            s1 += c[2] + c[3]; q1 += c[2] * c[2] + c[3] * c[3];
        }
#pragma unroll
        for (int o = 1; o <= 2; o <<= 1) {
            s0 += __shfl_xor_sync(0xffffffffu, s0, o);
            q0 += __shfl_xor_sync(0xffffffffu, q0, o);
            s1 += __shfl_xor_sync(0xffffffffu, s1, o);
            q1 += __shfl_xor_sync(0xffffffffu, q1, o);
        }
        if (tig == 0) {
            int r = wr * (MT * 16) + mt * 16 + gid;
            red [r * 4 + wc] = s0;  red2[r * 4 + wc] = q0;
            red [(r + 8) * 4 + wc] = s1;  red2[(r + 8) * 4 + wc] = q1;
        }
    }
    __syncthreads();

    float ea = 0.f, va = 0.f;
    if (EPI == 0) va = *a1;
    else { ea = *a1; va = *a2; }
    float c2 = 3.0f + va;

#pragma unroll
    for (int mt = 0; mt < MT; mt++) {
        int rl0 = wr * (MT * 16) + mt * 16 + gid;
        float mu[2], var[2];
#pragma unroll
        for (int h = 0; h < 2; h++) {
            int rl = rl0 + 8 * h;
            float S  = red [rl * 4] + red [rl * 4 + 1] + red [rl * 4 + 2] + red [rl * 4 + 3];
            float S2 = red2[rl * 4] + red2[rl * 4 + 1] + red2[rl * 4 + 2] + red2[rl * 4 + 3];
            mu[h]  = S * (1.0f / Dd);
            var[h] = S2 * (1.0f / Dd) - mu[h] * mu[h];
        }
        float rsA[2], rsB[2], rsC[2];
#pragma unroll
        for (int h = 0; h < 2; h++) {
            rsA[h] = rsqrtf(var[h] + LNEPS);
            if (EPI == 1) {
                rsB[h] = 2.0f * rsqrtf(4.0f * var[h] + LNEPS);
                rsC[h] = c2 * rsqrtf(c2 * c2 * var[h] + LNEPS);
            }
        }
#pragma unroll
        for (int nt = 0; nt < 8; nt++) {
            int col0 = wc * 64 + nt * 8 + 2 * tig;
            float gg0 = g[col0], gg1 = g[col0 + 1];
            float bb0 = bt[col0], bb1 = bt[col0 + 1];
#pragma unroll
            for (int h = 0; h < 2; h++) {
                size_t ro = (size_t)(i0 + rl0 + 8 * h) * Dd + col0;
                float dx0 = acc[mt][nt][2 * h]     - mu[h];
                float dx1 = acc[mt][nt][2 * h + 1] - mu[h];
                if (EPI == 0) {
                    float y0 = dx0 * rsA[h] * gg0 + bb0;
                    float y1 = dx1 * rsA[h] * gg1 + bb1;
                    out1[ro]     = round_tf32(y0);
                    out1[ro + 1] = round_tf32(y1);
                    out2[ro]     = c2 * y0;
                    out2[ro + 1] = c2 * y1;
                } else {
                    float f0 = aux[ro], f1 = aux[ro + 1];
                    float ya0 = dx0 * rsA[h] * gg0 + bb0, ya1 = dx1 * rsA[h] * gg1 + bb1;
                    float yb0 = dx0 * rsB[h] * gg0 + bb0, yb1 = dx1 * rsB[h] * gg1 + bb1;
                    float yc0 = dx0 * rsC[h] * gg0 + bb0, yc1 = dx1 * rsC[h] * gg1 + bb1;
                    float n0 = (1.0f + ea) * f0 + (1.0f - ea) * ya0;
                    n0 = (1.0f + ea) * n0 + (1.0f - ea) * yb0;
                    n0 = (1.0f + ea) * n0 + (1.0f - ea) * yc0;
                    float n1 = (1.0f + ea) * f1 + (1.0f - ea) * ya1;
                    n1 = (1.0f + ea) * n1 + (1.0f - ea) * yb1;
                    n1 = (1.0f + ea) * n1 + (1.0f - ea) * yc1;
                    out1[ro]     = n0;
                    out1[ro + 1] = n1;
                }
            }
        }
    }
}

// ============================================================================
// tf32 flash attention + embedded inc->out_inc copy + csum zeroing.
// ============================================================================
__global__ void __launch_bounds__(256, 2) attn_tf32_kernel(
    const float* __restrict__ qkv, float* __restrict__ ao,
    const float* __restrict__ inc, float* __restrict__ out_inc,
    float* __restrict__ csum)
{
    __shared__ unsigned Qs[64][36];
    __shared__ unsigned Ks[2][64][36];
    __shared__ unsigned Vs[2][64][36];   // [key][d]
    __shared__ unsigned Ps[64][68];      // exp(S) as tf32 bits
    __shared__ float    lrow[64];

    int bh = blockIdx.y; int b = bh >> 3; int h = bh & 7;
    int q0 = blockIdx.x * 64;
    int tid = threadIdx.x;
    int warp = tid >> 5, lane = tid & 31, gid = lane >> 2, tig = lane & 3;
    int wm = warp >> 2, wn = warp & 3;       // S-mma 2x4
    int wm2 = warp >> 1, wn2 = warp & 1;     // PV-mma 4x2
    const float scale = 0.17677669529663687f;

    // zero csum for step 4 (kernel-boundary ordering guarantees visibility)
    if (bh == 0 && blockIdx.x == 0) {
#pragma unroll
        for (int i = 0; i < (Bb * Dd) / 256; i++)
            csum[tid + i * 256] = 0.f;
    }

    size_t cbase = ((size_t)bh * gridDim.x + blockIdx.x) * 12288 + (size_t)tid * 4;

    auto load_kv = [&](int st, int kbase) {
#pragma unroll
        for (int i = 0; i < 2; i++) {
            int c = tid + i * 256;
            int m = c >> 3, j = (c & 7) << 2;
            const float* row = qkv + (size_t)(b * Mm + kbase + m) * D3 + h * DHd + j;
            cp_async16(&Ks[st][m][j], row + Dd);
            cp_async16(&Vs[st][m][j], row + 2 * Dd);
        }
        CP_COMMIT();
    };

#pragma unroll
    for (int i = 0; i < 2; i++) {
        int c = tid + i * 256;
        int m = c >> 3, j = (c & 7) << 2;
        cp_async16(&Qs[m][j], qkv + (size_t)(b * Mm + q0 + m) * D3 + h * DHd + j);
    }
    load_kv(0, 0);
    if (tid < 64) lrow[tid] = 0.f;

    float o[2][4] = {};
    int srow = tid >> 2, squad = tid & 3;

    for (int kt = 0; kt < Mm / 64; kt++) {
        int cur = kt & 1;
        asm volatile("cp.async.wait_group 0;");
        __syncthreads();
        if (kt + 1 < Mm / 64) load_kv(cur ^ 1, (kt + 1) * 64);

        float4 cpv;
        bool do_cp = (kt < 12);
        size_t coff = cbase + (size_t)kt * 1024;
        if (do_cp) cpv = *(const float4*)(inc + coff);

        float s[2][2][4] = {};
#pragma unroll
        for (int ks = 0; ks < 4; ks++) {
            int kk = ks * 8;
            unsigned a[2][4], bfr[2][2];
#pragma unroll
            for (int mt = 0; mt < 2; mt++) {
                int rb = wm * 32 + mt * 16;
                a[mt][0] = Qs[rb + gid    ][kk + tig];
                a[mt][1] = Qs[rb + gid + 8][kk + tig];
                a[mt][2] = Qs[rb + gid    ][kk + tig + 4];
                a[mt][3] = Qs[rb + gid + 8][kk + tig + 4];
            }
#pragma unroll
            for (int nt = 0; nt < 2; nt++) {
                int nb = wn * 16 + nt * 8;
                bfr[nt][0] = Ks[cur][nb + gid][kk + tig];
                bfr[nt][1] = Ks[cur][nb + gid][kk + tig + 4];
            }
#pragma unroll
            for (int mt = 0; mt < 2; mt++)
#pragma unroll
                for (int nt = 0; nt < 2; nt++)
                    mma_tf32(s[mt][nt], a[mt], bfr[nt]);
        }

#pragma unroll
        for (int mt = 0; mt < 2; mt++) {
            int r0 = wm * 32 + mt * 16 + gid;
#pragma unroll
            for (int nt = 0; nt < 2; nt++) {
                int c0 = wn * 16 + nt * 8 + 2 * tig;
                Ps[r0    ][c0    ] = f2tf32(__expf(s[mt][nt][0] * scale));
                Ps[r0    ][c0 + 1] = f2tf32(__expf(s[mt][nt][1] * scale));
                Ps[r0 + 8][c0    ] = f2tf32(__expf(s[mt][nt][2] * scale));
                Ps[r0 + 8][c0 + 1] = f2tf32(__expf(s[mt][nt][3] * scale));
            }
        }
        __syncthreads();

        {
            float sm = 0.f;
#pragma unroll
            for (int j = 0; j < 16; j++)
                sm += __uint_as_float(Ps[srow][squad * 16 + j]);
            sm += __shfl_xor_sync(0xffffffffu, sm, 1);
            sm += __shfl_xor_sync(0xffffffffu, sm, 2);
            if (squad == 0) lrow[srow] += sm;
        }

        {
            int rb2 = wm2 * 16;
#pragma unroll
            for (int ks = 0; ks < 8; ks++) {
                int kk = ks * 8;
                unsigned a[4], bfr[2][2];
                a[0] = Ps[rb2 + gid    ][kk + tig];
                a[1] = Ps[rb2 + gid + 8][kk + tig];
                a[2] = Ps[rb2 + gid    ][kk + tig + 4];
                a[3] = Ps[rb2 + gid + 8][kk + tig + 4];
#pragma unroll
                for (int nt = 0; nt < 2; nt++) {
                    int nb = wn2 * 16 + nt * 8;
                    bfr[nt][0] = Vs[cur][kk + tig    ][nb + gid];
                    bfr[nt][1] = Vs[cur][kk + tig + 4][nb + gid];
                }
#pragma unroll
                for (int nt = 0; nt < 2; nt++)
                    mma_tf32(o[nt], a, bfr[nt]);
            }
        }

        if (do_cp) *(float4*)(out_inc + coff) = cpv;
    }
    __syncthreads();

    int r0 = wm2 * 16 + gid;
    float inv0 = 1.0f / lrow[r0];
    float inv8 = 1.0f / lrow[r0 + 8];
#pragma unroll
    for (int nt = 0; nt < 2; nt++) {
        int c0 = wn2 * 16 + nt * 8 + 2 * tig;
        size_t base0 = (size_t)(b * Mm + q0 + r0) * Dd + h * DHd + c0;
        size_t base8 = (size_t)(b * Mm + q0 + r0 + 8) * Dd + h * DHd + c0;
        ao[base0]     = round_tf32(o[nt][0] * inv0);
        ao[base0 + 1] = round_tf32(o[nt][1] * inv0);
        ao[base8]     = round_tf32(o[nt][2] * inv8);
        ao[base8 + 1] = round_tf32(o[nt][3] * inv8);
    }
}

// ============================================================================
extern "C" void kernel_launch(void* const* d_in, const int* in_sizes, int n_in,
                              void* d_out, int out_size) {
    const float* features = (const float*)d_in[0];
    const float* inc      = (const float*)d_in[1];
    const float* vc_Win   = (const float*)d_in[2];
    const float* vc_bin   = (const float*)d_in[3];
    const float* vc_Wout  = (const float*)d_in[4];
    const float* vc_bout  = (const float*)d_in[5];
    const float* vc_Wproj = (const float*)d_in[6];
    const float* vc_ln_g  = (const float*)d_in[7];
    const float* vc_ln_b  = (const float*)d_in[8];
    const float* vc_alpha = (const float*)d_in[9];
    const float* ec_Wproj = (const float*)d_in[14];
    const float* ec_ln_g  = (const float*)d_in[15];
    const float* ec_ln_b  = (const float*)d_in[16];
    const float* ec_alpha = (const float*)d_in[17];

    float* out      = (float*)d_out;
    float* out_node = out;
    float* out_edge = out + (size_t)Bb * Mm * Dd;
    float* out_inc  = out_edge + (size_t)Bb * Ee * Dd;

    float *qkv, *ao, *attn, *S, *E0, *wef, *csum;
    cudaGetSymbolAddress((void**)&qkv,   g_qkv);
    cudaGetSymbolAddress((void**)&ao,    g_ao);
    cudaGetSymbolAddress((void**)&attn,  g_attn);
    cudaGetSymbolAddress((void**)&S,     g_S);
    cudaGetSymbolAddress((void**)&E0,    g_E0);
    cudaGetSymbolAddress((void**)&wef,   g_wef);
    cudaGetSymbolAddress((void**)&csum,  g_csum);

    // 1) QKV = features @ vc_Win^T + vc_bin  (A,B rounded at fragment read)
    gemm_tf32_kernel<3, 0, 0, true, true, false, true, true>
        <<<dim3(D3 / 64, (Bb * Mm) / 128, 1), 128>>>(
        features, vc_Win, vc_bin, qkv, Bb * Mm, D3, Dd, Dd, Dd, 0, 0, 0, nullptr);

    // 2) flash attention -> ao (rounded) + inc passthrough copy + csum zero
    attn_tf32_kernel<<<dim3(Mm / 64, Bb * Hh), 256>>>(qkv, ao, inc, out_inc, csum);

    // 3) attn = ao @ vc_Wout^T + vc_bout (rounded; B rounded at read)
    gemm_tf32_kernel<3, 0, 0, true, true, false, false, true>
        <<<dim3(Dd / 64, (Bb * Mm) / 128, 1), 128>>>(
        ao, vc_Wout, vc_bout, attn, Bb * Mm, Dd, Dd, Dd, Dd, 0, 0, 0, nullptr);

    // 4) S = inc^T @ attn + fused exp column sums — 5-stage ring (K=1024)
    gemm_tf32_kernel<5, 1, 1, false, false, true, false, false>
        <<<dim3(Dd / 64, Ee / 128, Bb), 128>>>(
        inc, attn, nullptr, S, Ee, Dd, Mm, Ee, Dd,
        (long)Mm * Ee, (long)Mm * Dd, (long)Ee * Dd, csum);

    // 6+7) fused: edge-weight transform + (edge @ vc_Wproj^T) -> LN -> E0 + out_edge
    gemm_ln_kernel<2, 0><<<dim3(1, (Bb * Ee) / 64), 256>>>(
        S, vc_Wproj, vc_ln_g, vc_ln_b, vc_alpha, nullptr, csum, E0, out_edge);

    // 8) wef = inc @ E0 (rounded) — 4-stage ring (K=1536)
    gemm_tf32_kernel<4, 0, 1, false, true, false, false, false>
        <<<dim3(Dd / 64, Mm / 128, Bb), 128>>>(
        inc, E0, nullptr, wef, Mm, Dd, Ee, Ee, Dd,
        (long)Mm * Ee, (long)Ee * Dd, (long)Mm * Dd, nullptr);

    // 9) fused: (wef @ ec_Wproj^T) -> LN -> 3-step recurrence -> out_node
    gemm_ln_kernel<2, 1><<<dim3(1, (Bb * Mm) / 64), 256>>>(
        wef, ec_Wproj, ec_ln_g, ec_ln_b, ec_alpha, vc_alpha, features, out_node, nullptr);
}